// round 9
// baseline (speedup 1.0000x reference)
#include <cuda_runtime.h>
#include <cuda_bf16.h>
#include <cstdint>

// Problem constants (shapes fixed by the reference: N=20000, E=100000)
#define NMAX 20000
#define EMAX 100000
constexpr int IN_DIM = 128;
constexpr int HID    = 64;
constexpr int LAT    = 32;
constexpr int EDIM   = 16;

// ---------------- edge kernel geometry --------------------------------------
// 128 threads = 4 warps; 128 edges per tile; warp w owns 32 edges (TWO m16
// A-tiles) so every B-fragment ldmatrix feeds 12 MMAs instead of 6.
// Persistent CTAs (grid = 148*3 = 444) pull tiles from a global ticket; B
// cp.async double-buffer runs continuously across tile boundaries.
constexpr int B_CHUNK_BYTES = 256 * 48;          // per term: 12288
constexpr int B_BIAS_OFF    = 2 * B_CHUNK_BYTES; // 24576
constexpr int B_SLOT_BYTES  = B_BIAS_OFF + 1024; // hi + lo + bias: 25600
constexpr int NCHUNK        = 16;
constexpr int EDGE_GRID     = 444;               // 148 SMs * 3 CTAs/SM

// dynamic smem layout (16B aligned blocks). No H stage (h read via LDG from L2).
constexpr int SMB_A    = 0;                       // 2 terms * 128*48 = 12288
constexpr int SMB_B    = 12288;                   // 2 slots * 25600 = 51200
constexpr int SMEM_EDGE = SMB_B + 2 * B_SLOT_BYTES;   // 63488 (3 CTAs/SM)

// ---------------- scratch (device globals; no cudaMalloc allowed) -----------
__device__ float g_h[NMAX * HID];
__device__ float g_num[NMAX * HID];
__device__ float g_cnt[NMAX];
__device__ int   g_src[EMAX];
__device__ int   g_dst[EMAX];
__device__ int   g_is64;
__device__ int   g_ticket;
__device__ __align__(16) unsigned char g_Bp[NCHUNK * B_SLOT_BYTES]; // 400KB

// ---------------- helpers ----------------------------------------------------
typedef unsigned long long u64;

__device__ __forceinline__ u64 pk2(float x, float y) {
    u64 r; asm("mov.b64 %0,{%1,%2};" : "=l"(r) : "f"(x), "f"(y)); return r;
}
__device__ __forceinline__ void upk2(u64 v, float& x, float& y) {
    asm("mov.b64 {%0,%1},%2;" : "=f"(x), "=f"(y) : "l"(v));
}
__device__ __forceinline__ u64 ffma2(u64 a, u64 b, u64 c) {
    u64 d; asm("fma.rn.f32x2 %0,%1,%2,%3;" : "=l"(d) : "l"(a), "l"(b), "l"(c)); return d;
}
__device__ __forceinline__ unsigned smem_u32(const void* p) {
    return (unsigned)__cvta_generic_to_shared(p);
}
__device__ __forceinline__ void cpasync16(unsigned dst, const void* src) {
    asm volatile("cp.async.ca.shared.global [%0], [%1], 16;" :: "r"(dst), "l"(src));
}
#define CP_COMMIT() asm volatile("cp.async.commit_group;" ::: "memory")
#define CP_WAIT0()  asm volatile("cp.async.wait_group 0;" ::: "memory")

#define LDMX4(r, addr) \
    asm volatile("ldmatrix.sync.aligned.m8n8.x4.shared.b16 {%0,%1,%2,%3},[%4];" \
                 : "=r"((r)[0]), "=r"((r)[1]), "=r"((r)[2]), "=r"((r)[3]) : "r"(addr))

#define MMA_BF16(c0, c1, c2, c3, a, b0, b1) \
    asm volatile("mma.sync.aligned.m16n8k16.row.col.f32.bf16.bf16.f32 " \
                 "{%0,%1,%2,%3},{%4,%5,%6,%7},{%8,%9},{%0,%1,%2,%3};" \
                 : "+f"(c0), "+f"(c1), "+f"(c2), "+f"(c3) \
                 : "r"((a)[0]), "r"((a)[1]), "r"((a)[2]), "r"((a)[3]), \
                   "r"(b0), "r"(b1))

// ---------------- setup: detect + zero + prep + ticket reset -----------------
__global__ void setup_kernel(const int* __restrict__ ei,
                             const float* __restrict__ kw,
                             const float* __restrict__ kb, int N) {
    int gtid = blockIdx.x * 256 + threadIdx.x;
    int gsz  = gridDim.x * 256;
    if (gtid == 0) {
        int is64 = 1;
#pragma unroll
        for (int k = 0; k < 32; k++)
            if (ei[2 * k + 1] != 0) is64 = 0;
        g_is64 = is64;
        g_ticket = 0;
    }
    int tot = N * HID;
    for (int i = gtid; i < tot; i += gsz) g_num[i] = 0.f;
    for (int j = gtid; j < N; j += gsz)   g_cnt[j] = 0.f;
    for (int idx = gtid; idx < 4096 * 16; idx += gsz) {
        int n = idx >> 4, k = idx & 15;
        float v = kw[(size_t)k * 4096 + n];
        __nv_bfloat16 hi = __float2bfloat16_rn(v);
        __nv_bfloat16 lo = __float2bfloat16_rn(v - __bfloat162float(hi));
        int c = n >> 8, nl = n & 255;
        size_t base = (size_t)c * B_SLOT_BYTES + (size_t)nl * 48 + (size_t)k * 2;
        *(__nv_bfloat16*)(g_Bp + base)                 = hi;
        *(__nv_bfloat16*)(g_Bp + base + B_CHUNK_BYTES) = lo;
    }
    for (int n = gtid; n < 4096; n += gsz) {
        int c = n >> 8, nl = n & 255;
        *(float*)(g_Bp + (size_t)c * B_SLOT_BYTES + B_BIAS_OFF + (size_t)nl * 4) = kb[n];
    }
}

__global__ void convert_kernel(const void* __restrict__ ei, int E) {
    int e = blockIdx.x * blockDim.x + threadIdx.x;
    if (e >= E) return;
    int s, d;
    if (g_is64) {
        const long long* p = (const long long*)ei;
        s = (int)p[e]; d = (int)p[E + e];
    } else {
        const int* p = (const int*)ei;
        s = p[e]; d = p[E + e];
    }
    g_src[e] = s; g_dst[e] = d;
    atomicAdd(&g_cnt[d], 1.f);
}

// ---------------- h = relu(x @ lin_in_w + lin_in_b) -------------------------
__global__ void __launch_bounds__(128) hin_kernel(
    const float* __restrict__ x, const float* __restrict__ w,
    const float* __restrict__ b, int N) {
    __shared__ u64   ws2[IN_DIM][32];   // (w[d][2p], w[d][2p+1])
    __shared__ float xs[16][IN_DIM];
    int tid = threadIdx.x;
    for (int i = tid; i < IN_DIM * 32; i += 128)
        ((u64*)ws2)[i] = ((const u64*)w)[i];
    int base = blockIdx.x * 16;
    for (int i = tid; i < 16 * 32; i += 128) {
        int nl = i >> 5, j = i & 31;
        int n = base + nl;
        if (n < N) ((float4*)xs[nl])[j] = ((const float4*)(x + (size_t)n * IN_DIM))[j];
    }
    __syncthreads();
    int p = tid & 31, g = tid >> 5;
    float2 b2 = ((const float2*)b)[p];
    u64 bias2 = pk2(b2.x, b2.y);
    u64 acc0 = bias2, acc1 = bias2, acc2 = bias2, acc3 = bias2;
#pragma unroll 8
    for (int d = 0; d < IN_DIM; d++) {
        u64 w2 = ws2[d][p];
        acc0 = ffma2(pk2(xs[g][d],      xs[g][d]),      w2, acc0);
        acc1 = ffma2(pk2(xs[g + 4][d],  xs[g + 4][d]),  w2, acc1);
        acc2 = ffma2(pk2(xs[g + 8][d],  xs[g + 8][d]),  w2, acc2);
        acc3 = ffma2(pk2(xs[g + 12][d], xs[g + 12][d]), w2, acc3);
    }
    u64 accs[4] = {acc0, acc1, acc2, acc3};
#pragma unroll
    for (int q = 0; q < 4; q++) {
        int n = base + g + 4 * q;
        if (n < N) {
            float v0, v1; upk2(accs[q], v0, v1);
            float2 r; r.x = fmaxf(v0, 0.f); r.y = fmaxf(v1, 0.f);
            *(float2*)(g_h + (size_t)n * HID + 2 * p) = r;
        }
    }
}

// ---------------- fused edge kernel (mma.sync bf16 3-term, persistent) -------
__device__ __forceinline__ void stage_A(unsigned char* sm,
                                        const float* __restrict__ edge_attr,
                                        int tile, int E, int tid) {
    int e = tile * 128 + tid;
    float va[16];
    if (e < E) {
        const float4* p = (const float4*)(edge_attr + (size_t)e * EDIM);
#pragma unroll
        for (int i = 0; i < 4; i++) {
            float4 q4 = p[i];
            va[4*i] = q4.x; va[4*i+1] = q4.y; va[4*i+2] = q4.z; va[4*i+3] = q4.w;
        }
    } else {
#pragma unroll
        for (int i = 0; i < 16; i++) va[i] = 0.f;
    }
#pragma unroll
    for (int k = 0; k < 8; k++) {
        float v0 = va[2*k], v1 = va[2*k+1];
        __nv_bfloat16 h0 = __float2bfloat16_rn(v0);
        __nv_bfloat16 h1 = __float2bfloat16_rn(v1);
        __nv_bfloat162 hp; hp.x = h0; hp.y = h1;
        __nv_bfloat162 lp;
        lp.x = __float2bfloat16_rn(v0 - __bfloat162float(h0));
        lp.y = __float2bfloat16_rn(v1 - __bfloat162float(h1));
        *(__nv_bfloat162*)(sm + SMB_A + tid * 48 + k * 4)        = hp;
        *(__nv_bfloat162*)(sm + SMB_A + 6144 + tid * 48 + k * 4) = lp;
    }
}

__global__ void __launch_bounds__(128, 3) edge_kernel(
    const float* __restrict__ edge_attr, int E, int ntiles) {
    extern __shared__ __align__(16) unsigned char sm[];
    __shared__ int s_tile;
    unsigned sb = smem_u32(sm);
    int tid = threadIdx.x, lane = tid & 31, w = tid >> 5;

    if (tid == 0) s_tile = atomicAdd(&g_ticket, 1);
    __syncthreads();
    int tile = s_tile;
    if (tile >= ntiles) return;

    stage_A(sm, edge_attr, tile, E, tid);

    // prefetch B chunk 0 -> slot 0
    for (int i = tid; i < B_SLOT_BYTES / 16; i += 128)
        cpasync16(sb + SMB_B + i * 16, g_Bp + i * 16);
    CP_COMMIT();
    CP_WAIT0();
    __syncthreads();

    int q = lane & 3;
    int row0 = lane >> 2;
    // warp owns edges [w*32, w*32+32): two m16 A-tiles (t0: rows 0-15, t1: 16-31)
    unsigned aaddr0 = sb + SMB_A +
        (unsigned)((w * 32 + (lane & 7) + ((lane >> 3) & 1) * 8) * 48 + (lane >> 4) * 16);
    unsigned aaddr1 = aaddr0 + 16 * 48;
    unsigned bext = (unsigned)((lane & 7) * 48 + ((lane & 8) ? 16 : 0)
                               + ((lane & 16) ? 384 : 0));

    int cc = 0;
    while (true) {
        // A fragments for this tile (register resident)
        unsigned a_hi0[4], a_lo0[4], a_hi1[4], a_lo1[4];
        LDMX4(a_hi0, aaddr0);
        LDMX4(a_lo0, aaddr0 + 6144);
        LDMX4(a_hi1, aaddr1);
        LDMX4(a_lo1, aaddr1 + 6144);

        int e0 = tile * 128 + w * 32 + row0;
        int e1 = e0 + 8, e2 = e0 + 16, e3 = e0 + 24;
        const float4* hp0 = (const float4*)(g_h + (size_t)((e0 < E) ? g_src[e0] : 0) * HID);
        const float4* hp1 = (const float4*)(g_h + (size_t)((e1 < E) ? g_src[e1] : 0) * HID);
        const float4* hp2 = (const float4*)(g_h + (size_t)((e2 < E) ? g_src[e2] : 0) * HID);
        const float4* hp3 = (const float4*)(g_h + (size_t)((e3 < E) ? g_src[e3] : 0) * HID);

        float msgA[16], msgB[16], msgC[16], msgD[16];
#pragma unroll
        for (int i = 0; i < 16; i++) { msgA[i] = 0.f; msgB[i] = 0.f; msgC[i] = 0.f; msgD[i] = 0.f; }

#pragma unroll 1
        for (int c = 0; c < NCHUNK; c++, cc++) {
            int slot = cc & 1;
            {   // prefetch next chunk in the tile-independent sequence
                int nc = (cc + 1) & 15;
                const unsigned char* src = g_Bp + (size_t)nc * B_SLOT_BYTES;
                unsigned dstb = sb + SMB_B + (unsigned)(((cc + 1) & 1) * B_SLOT_BYTES);
                for (int i = tid; i < B_SLOT_BYTES / 16; i += 128)
                    cpasync16(dstb + i * 16, src + i * 16);
                CP_COMMIT();
            }
            unsigned slotbase = sb + SMB_B + (unsigned)(slot * B_SLOT_BYTES);
            unsigned bhib  = slotbase + bext;
            unsigned biasb = slotbase + (unsigned)B_BIAS_OFF + (unsigned)(q * 8);
            float4 hv0 = __ldg(hp0 + c);
            float4 hv1 = __ldg(hp1 + c);
            float4 hv2 = __ldg(hp2 + c);
            float4 hv3 = __ldg(hp3 + c);
            float h0a[4] = {hv0.x, hv0.y, hv0.z, hv0.w};
            float h1a[4] = {hv1.x, hv1.y, hv1.z, hv1.w};
            float h2a[4] = {hv2.x, hv2.y, hv2.z, hv2.w};
            float h3a[4] = {hv3.x, hv3.y, hv3.z, hv3.w};
#pragma unroll
            for (int hb = 0; hb < 4; hb++) {
                float hs0 = h0a[hb], hs1 = h1a[hb], hs2 = h2a[hb], hs3 = h3a[hb];
#pragma unroll
                for (int jp = 0; jp < 4; jp++) {
                    int jj0 = hb * 8 + jp * 2;
                    unsigned ba = bhib + (unsigned)(jj0 * 384);
                    unsigned bh[4], bl[4];
                    LDMX4(bh, ba);
                    LDMX4(bl, ba + B_CHUNK_BYTES);
                    float bb0x, bb0y, bb1x, bb1y;
                    asm("ld.shared.v2.f32 {%0,%1},[%2];"
                        : "=f"(bb0x), "=f"(bb0y) : "r"(biasb + (unsigned)(jj0 * 32)));
                    asm("ld.shared.v2.f32 {%0,%1},[%2];"
                        : "=f"(bb1x), "=f"(bb1y) : "r"(biasb + (unsigned)(jj0 * 32 + 32)));
                    // 4 independent 3-MMA chains: (tile0,jj0) (tile0,jj1) (tile1,jj0) (tile1,jj1)
                    float c0 = bb0x, c1 = bb0y, c2 = bb0x, c3 = bb0y;
                    float d0 = bb1x, d1 = bb1y, d2 = bb1x, d3 = bb1y;
                    float f0 = bb0x, f1 = bb0y, f2 = bb0x, f3 = bb0y;
                    float g0 = bb1x, g1 = bb1y, g2 = bb1x, g3 = bb1y;
                    MMA_BF16(c0, c1, c2, c3, a_hi0, bh[0], bh[1]);
                    MMA_BF16(d0, d1, d2, d3, a_hi0, bh[2], bh[3]);
                    MMA_BF16(f0, f1, f2, f3, a_hi1, bh[0], bh[1]);
                    MMA_BF16(g0, g1, g2, g3, a_hi1, bh[2], bh[3]);
                    MMA_BF16(c0, c1, c2, c3, a_lo0, bh[0], bh[1]);
                    MMA_BF16(d0, d1, d2, d3, a_lo0, bh[2], bh[3]);
                    MMA_BF16(f0, f1, f2, f3, a_lo1, bh[0], bh[1]);
                    MMA_BF16(g0, g1, g2, g3, a_lo1, bh[2], bh[3]);
                    MMA_BF16(c0, c1, c2, c3, a_hi0, bl[0], bl[1]);
                    MMA_BF16(d0, d1, d2, d3, a_hi0, bl[2], bl[3]);
                    MMA_BF16(f0, f1, f2, f3, a_hi1, bl[0], bl[1]);
                    MMA_BF16(g0, g1, g2, g3, a_hi1, bl[2], bl[3]);
                    // epilogue: relu + h-weighted accumulate
                    int m = 4 * jp;
                    msgA[m]     = fmaf(hs0, fmaxf(c0, 0.f), msgA[m]);
                    msgA[m + 1] = fmaf(hs0, fmaxf(c1, 0.f), msgA[m + 1]);
                    msgB[m]     = fmaf(hs1, fmaxf(c2, 0.f), msgB[m]);
                    msgB[m + 1] = fmaf(hs1, fmaxf(c3, 0.f), msgB[m + 1]);
                    msgA[m + 2] = fmaf(hs0, fmaxf(d0, 0.f), msgA[m + 2]);
                    msgA[m + 3] = fmaf(hs0, fmaxf(d1, 0.f), msgA[m + 3]);
                    msgB[m + 2] = fmaf(hs1, fmaxf(d2, 0.f), msgB[m + 2]);
                    msgB[m + 3] = fmaf(hs1, fmaxf(d3, 0.f), msgB[m + 3]);
                    msgC[m]     = fmaf(hs2, fmaxf(f0, 0.f), msgC[m]);
                    msgC[m + 1] = fmaf(hs2, fmaxf(f1, 0.f), msgC[m + 1]);
                    msgD[m]     = fmaf(hs3, fmaxf(f2, 0.f), msgD[m]);
                    msgD[m + 1] = fmaf(hs3, fmaxf(f3, 0.f), msgD[m + 1]);
                    msgC[m + 2] = fmaf(hs2, fmaxf(g0, 0.f), msgC[m + 2]);
                    msgC[m + 3] = fmaf(hs2, fmaxf(g1, 0.f), msgC[m + 3]);
                    msgD[m + 2] = fmaf(hs3, fmaxf(g2, 0.f), msgD[m + 2]);
                    msgD[m + 3] = fmaf(hs3, fmaxf(g3, 0.f), msgD[m + 3]);
                }
            }
            CP_WAIT0();
            __syncthreads();
        }

        // scatter: each (edge, o) has a unique owner thread
        if (e0 < E) {
            float* d = g_num + (size_t)g_dst[e0] * HID + 2 * q;
#pragma unroll
            for (int i = 0; i < 8; i++) {
                atomicAdd(d + 8 * i,     msgA[2 * i]);
                atomicAdd(d + 8 * i + 1, msgA[2 * i + 1]);
            }
        }
        if (e1 < E) {
            float* d = g_num + (size_t)g_dst[e1] * HID + 2 * q;
#pragma unroll
            for (int i = 0; i < 8; i++) {
                atomicAdd(d + 8 * i,     msgB[2 * i]);
                atomicAdd(d + 8 * i + 1, msgB[2 * i + 1]);
            }
        }
        if (e2 < E) {
            float* d = g_num + (size_t)g_dst[e2] * HID + 2 * q;
#pragma unroll
            for (int i = 0; i < 8; i++) {
                atomicAdd(d + 8 * i,     msgC[2 * i]);
                atomicAdd(d + 8 * i + 1, msgC[2 * i + 1]);
            }
        }
        if (e3 < E) {
            float* d = g_num + (size_t)g_dst[e3] * HID + 2 * q;
#pragma unroll
            for (int i = 0; i < 8; i++) {
                atomicAdd(d + 8 * i,     msgD[2 * i]);
                atomicAdd(d + 8 * i + 1, msgD[2 * i + 1]);
            }
        }

        // next tile from the ticket; A smem safe to overwrite (all warps
        // consumed their fragments at the top of this iteration)
        if (tid == 0) s_tile = atomicAdd(&g_ticket, 1);
        __syncthreads();
        tile = s_tile;
        if (tile >= ntiles) break;
        stage_A(sm, edge_attr, tile, E, tid);
        __syncthreads();
    }
}

// ---------------- final: relu(h@root_w + num/cnt + conv_b) -> mu/logvar -----
__global__ void __launch_bounds__(256) final_kernel(
    const float* __restrict__ root_w, const float* __restrict__ conv_b,
    const float* __restrict__ mu_w, const float* __restrict__ mu_b,
    const float* __restrict__ lv_w, const float* __restrict__ lv_b,
    float* __restrict__ out, int N) {
    __shared__ float rw[HID][HID];
    __shared__ float mw[HID][LAT];
    __shared__ float lw[HID][LAT];
    __shared__ float hv[4][HID];
    __shared__ float tv[4][HID];
    int tid = threadIdx.x;
    for (int idx = tid; idx < HID * HID / 4; idx += 256)
        ((float4*)rw)[idx] = ((const float4*)root_w)[idx];
    for (int idx = tid; idx < HID * LAT / 4; idx += 256)
        ((float4*)mw)[idx] = ((const float4*)mu_w)[idx];
    for (int idx = tid; idx < HID * LAT / 4; idx += 256)
        ((float4*)lw)[idx] = ((const float4*)lv_w)[idx];
    __syncthreads();

    int g = tid >> 6;
    int o = tid & 63;
    float cb = conv_b[o];
    float hb = (o < LAT) ? mu_b[o] : lv_b[o - LAT];

    for (int nl = g; nl < 16; nl += 4) {
        int n = blockIdx.x * 16 + nl;
        bool valid = n < N;
        if (valid) hv[g][o] = g_h[(size_t)n * HID + o];
        asm volatile("bar.sync %0, 64;" :: "r"(g + 1) : "memory");
        if (valid) {
            float inv = 1.f / fmaxf(g_cnt[n], 1.f);
            float acc = cb + g_num[(size_t)n * HID + o] * inv;
#pragma unroll
            for (int h = 0; h < HID; h++) acc += hv[g][h] * rw[h][o];
            tv[g][o] = fmaxf(acc, 0.f);
        }
        asm volatile("bar.sync %0, 64;" :: "r"(g + 1) : "memory");
        if (valid) {
            if (o < LAT) {
                float m = hb;
#pragma unroll
                for (int k = 0; k < HID; k++) m += tv[g][k] * mw[k][o];
                out[(size_t)n * LAT + o] = m;
            } else {
                int l = o - LAT;
                float m = hb;
#pragma unroll
                for (int k = 0; k < HID; k++) m += tv[g][k] * lw[k][l];
                out[(size_t)N * LAT + (size_t)n * LAT + l] = m;
            }
        }
        asm volatile("bar.sync %0, 64;" :: "r"(g + 1) : "memory");
    }
}

// ---------------- launcher ---------------------------------------------------
extern "C" void kernel_launch(void* const* d_in, const int* in_sizes, int n_in,
                              void* d_out, int out_size) {
    const float* x      = (const float*)d_in[0];
    const void*  ei     = d_in[1];
    const float* ea     = (const float*)d_in[2];
    const float* lin_w  = (const float*)d_in[3];
    const float* lin_b  = (const float*)d_in[4];
    const float* ker_w  = (const float*)d_in[5];
    const float* ker_b  = (const float*)d_in[6];
    const float* root_w = (const float*)d_in[7];
    const float* conv_b = (const float*)d_in[8];
    const float* mu_w   = (const float*)d_in[9];
    const float* mu_b   = (const float*)d_in[10];
    const float* lv_w   = (const float*)d_in[11];
    const float* lv_b   = (const float*)d_in[12];

    int N = in_sizes[0] / IN_DIM;
    int E = in_sizes[1] / 2;
    if (N > NMAX) N = NMAX;
    if (E > EMAX) E = EMAX;

    cudaFuncSetAttribute(edge_kernel, cudaFuncAttributeMaxDynamicSharedMemorySize,
                         SMEM_EDGE);

    int ntiles = (E + 127) / 128;
    int grid   = (ntiles < EDGE_GRID) ? ntiles : EDGE_GRID;

    setup_kernel<<<640, 256>>>((const int*)ei, ker_w, ker_b, N);
    convert_kernel<<<(E + 255) / 256, 256>>>(ei, E);
    hin_kernel<<<(N + 15) / 16, 128>>>(x, lin_w, lin_b, N);
    edge_kernel<<<grid, 128, SMEM_EDGE>>>(ea, E, ntiles);
    final_kernel<<<(N + 15) / 16, 256>>>(root_w, conv_b, mu_w, mu_b, lv_w, lv_b,
                                         (float*)d_out, N);
}

// round 10
// speedup vs baseline: 1.2026x; 1.2026x over previous
#include <cuda_runtime.h>
#include <cuda_bf16.h>
#include <cstdint>

// Problem constants (shapes fixed by the reference: N=20000, E=100000)
#define NMAX 20000
#define EMAX 100000
constexpr int IN_DIM = 128;
constexpr int HID    = 64;
constexpr int LAT    = 32;
constexpr int EDIM   = 16;

// ---------------- edge kernel geometry --------------------------------------
// 128 threads = 4 warps; 128 edges per tile; warp w owns 32 edges (two m16
// A-tiles) -> every B-fragment ldmatrix feeds 8 MMAs (2-term split).
// 2-term bf16 split: W ~= (ahi + alo) * bhi  (b quantization error ~2^-9,
// attenuated ~7x through the aggregation chain -> final rel_err ~1.5e-4).
// Persistent CTAs (grid = 444) pull tiles from a global ticket; B cp.async
// double-buffer runs continuously across tile boundaries.
constexpr int B_CHUNK_BYTES = 256 * 48;          // bh image: 12288
constexpr int B_BIAS_OFF    = B_CHUNK_BYTES;     // 12288
constexpr int B_SLOT_BYTES  = B_BIAS_OFF + 1024; // bh + bias: 13312
constexpr int NCHUNK        = 16;
constexpr int EDGE_GRID     = 444;               // 148 SMs * 3 CTAs/SM

// dynamic smem layout (16B aligned blocks). No H stage (h read via LDG from L2).
constexpr int SMB_A    = 0;                       // 2 terms * 128*48 = 12288
constexpr int SMB_B    = 12288;                   // 2 slots * 13312 = 26624
constexpr int SMEM_EDGE = SMB_B + 2 * B_SLOT_BYTES;   // 38912

// ---------------- scratch (device globals; no cudaMalloc allowed) -----------
__device__ float g_h[NMAX * HID];
__device__ float g_num[NMAX * HID];
__device__ float g_cnt[NMAX];
__device__ int   g_src[EMAX];
__device__ int   g_dst[EMAX];
__device__ int   g_is64;
__device__ int   g_ticket;
__device__ __align__(16) unsigned char g_Bp[NCHUNK * B_SLOT_BYTES]; // 208KB

// ---------------- helpers ----------------------------------------------------
typedef unsigned long long u64;

__device__ __forceinline__ u64 pk2(float x, float y) {
    u64 r; asm("mov.b64 %0,{%1,%2};" : "=l"(r) : "f"(x), "f"(y)); return r;
}
__device__ __forceinline__ void upk2(u64 v, float& x, float& y) {
    asm("mov.b64 {%0,%1},%2;" : "=f"(x), "=f"(y) : "l"(v));
}
__device__ __forceinline__ u64 ffma2(u64 a, u64 b, u64 c) {
    u64 d; asm("fma.rn.f32x2 %0,%1,%2,%3;" : "=l"(d) : "l"(a), "l"(b), "l"(c)); return d;
}
__device__ __forceinline__ unsigned smem_u32(const void* p) {
    return (unsigned)__cvta_generic_to_shared(p);
}
__device__ __forceinline__ void cpasync16(unsigned dst, const void* src) {
    asm volatile("cp.async.ca.shared.global [%0], [%1], 16;" :: "r"(dst), "l"(src));
}
#define CP_COMMIT() asm volatile("cp.async.commit_group;" ::: "memory")
#define CP_WAIT0()  asm volatile("cp.async.wait_group 0;" ::: "memory")

#define LDMX4(r, addr) \
    asm volatile("ldmatrix.sync.aligned.m8n8.x4.shared.b16 {%0,%1,%2,%3},[%4];" \
                 : "=r"((r)[0]), "=r"((r)[1]), "=r"((r)[2]), "=r"((r)[3]) : "r"(addr))

#define MMA_BF16(c0, c1, c2, c3, a, b0, b1) \
    asm volatile("mma.sync.aligned.m16n8k16.row.col.f32.bf16.bf16.f32 " \
                 "{%0,%1,%2,%3},{%4,%5,%6,%7},{%8,%9},{%0,%1,%2,%3};" \
                 : "+f"(c0), "+f"(c1), "+f"(c2), "+f"(c3) \
                 : "r"((a)[0]), "r"((a)[1]), "r"((a)[2]), "r"((a)[3]), \
                   "r"(b0), "r"(b1))

// ---------------- setup: detect + zero + prep + ticket reset -----------------
__global__ void setup_kernel(const int* __restrict__ ei,
                             const float* __restrict__ kw,
                             const float* __restrict__ kb, int N) {
    int gtid = blockIdx.x * 256 + threadIdx.x;
    int gsz  = gridDim.x * 256;
    if (gtid == 0) {
        int is64 = 1;
#pragma unroll
        for (int k = 0; k < 32; k++)
            if (ei[2 * k + 1] != 0) is64 = 0;
        g_is64 = is64;
        g_ticket = 0;
    }
    int tot = N * HID;
    for (int i = gtid; i < tot; i += gsz) g_num[i] = 0.f;
    for (int j = gtid; j < N; j += gsz)   g_cnt[j] = 0.f;
    // prep B image: bf16(round-nearest) with 48B row stride (pad stays 0-init)
    for (int idx = gtid; idx < 4096 * 16; idx += gsz) {
        int n = idx >> 4, k = idx & 15;
        float v = kw[(size_t)k * 4096 + n];
        int c = n >> 8, nl = n & 255;
        *(__nv_bfloat16*)(g_Bp + (size_t)c * B_SLOT_BYTES + (size_t)nl * 48
                          + (size_t)k * 2) = __float2bfloat16_rn(v);
    }
    for (int n = gtid; n < 4096; n += gsz) {
        int c = n >> 8, nl = n & 255;
        *(float*)(g_Bp + (size_t)c * B_SLOT_BYTES + B_BIAS_OFF + (size_t)nl * 4) = kb[n];
    }
}

__global__ void convert_kernel(const void* __restrict__ ei, int E) {
    int e = blockIdx.x * blockDim.x + threadIdx.x;
    if (e >= E) return;
    int s, d;
    if (g_is64) {
        const long long* p = (const long long*)ei;
        s = (int)p[e]; d = (int)p[E + e];
    } else {
        const int* p = (const int*)ei;
        s = p[e]; d = p[E + e];
    }
    g_src[e] = s; g_dst[e] = d;
    atomicAdd(&g_cnt[d], 1.f);
}

// ---------------- h = relu(x @ lin_in_w + lin_in_b) -------------------------
__global__ void __launch_bounds__(128) hin_kernel(
    const float* __restrict__ x, const float* __restrict__ w,
    const float* __restrict__ b, int N) {
    __shared__ u64   ws2[IN_DIM][32];   // (w[d][2p], w[d][2p+1])
    __shared__ float xs[16][IN_DIM];
    int tid = threadIdx.x;
    for (int i = tid; i < IN_DIM * 32; i += 128)
        ((u64*)ws2)[i] = ((const u64*)w)[i];
    int base = blockIdx.x * 16;
    for (int i = tid; i < 16 * 32; i += 128) {
        int nl = i >> 5, j = i & 31;
        int n = base + nl;
        if (n < N) ((float4*)xs[nl])[j] = ((const float4*)(x + (size_t)n * IN_DIM))[j];
    }
    __syncthreads();
    int p = tid & 31, g = tid >> 5;
    float2 b2 = ((const float2*)b)[p];
    u64 bias2 = pk2(b2.x, b2.y);
    u64 acc0 = bias2, acc1 = bias2, acc2 = bias2, acc3 = bias2;
#pragma unroll 8
    for (int d = 0; d < IN_DIM; d++) {
        u64 w2 = ws2[d][p];
        acc0 = ffma2(pk2(xs[g][d],      xs[g][d]),      w2, acc0);
        acc1 = ffma2(pk2(xs[g + 4][d],  xs[g + 4][d]),  w2, acc1);
        acc2 = ffma2(pk2(xs[g + 8][d],  xs[g + 8][d]),  w2, acc2);
        acc3 = ffma2(pk2(xs[g + 12][d], xs[g + 12][d]), w2, acc3);
    }
    u64 accs[4] = {acc0, acc1, acc2, acc3};
#pragma unroll
    for (int q = 0; q < 4; q++) {
        int n = base + g + 4 * q;
        if (n < N) {
            float v0, v1; upk2(accs[q], v0, v1);
            float2 r; r.x = fmaxf(v0, 0.f); r.y = fmaxf(v1, 0.f);
            *(float2*)(g_h + (size_t)n * HID + 2 * p) = r;
        }
    }
}

// ---------------- fused edge kernel (mma.sync bf16 2-term, persistent) -------
__device__ __forceinline__ void stage_A(unsigned char* sm,
                                        const float* __restrict__ edge_attr,
                                        int tile, int E, int tid) {
    int e = tile * 128 + tid;
    float va[16];
    if (e < E) {
        const float4* p = (const float4*)(edge_attr + (size_t)e * EDIM);
#pragma unroll
        for (int i = 0; i < 4; i++) {
            float4 q4 = p[i];
            va[4*i] = q4.x; va[4*i+1] = q4.y; va[4*i+2] = q4.z; va[4*i+3] = q4.w;
        }
    } else {
#pragma unroll
        for (int i = 0; i < 16; i++) va[i] = 0.f;
    }
#pragma unroll
    for (int k = 0; k < 8; k++) {
        float v0 = va[2*k], v1 = va[2*k+1];
        __nv_bfloat16 h0 = __float2bfloat16_rn(v0);
        __nv_bfloat16 h1 = __float2bfloat16_rn(v1);
        __nv_bfloat162 hp; hp.x = h0; hp.y = h1;
        __nv_bfloat162 lp;
        lp.x = __float2bfloat16_rn(v0 - __bfloat162float(h0));
        lp.y = __float2bfloat16_rn(v1 - __bfloat162float(h1));
        *(__nv_bfloat162*)(sm + SMB_A + tid * 48 + k * 4)        = hp;
        *(__nv_bfloat162*)(sm + SMB_A + 6144 + tid * 48 + k * 4) = lp;
    }
}

__global__ void __launch_bounds__(128, 3) edge_kernel(
    const float* __restrict__ edge_attr, int E, int ntiles) {
    extern __shared__ __align__(16) unsigned char sm[];
    __shared__ int s_tile;
    unsigned sb = smem_u32(sm);
    int tid = threadIdx.x, lane = tid & 31, w = tid >> 5;

    if (tid == 0) s_tile = atomicAdd(&g_ticket, 1);
    __syncthreads();
    int tile = s_tile;
    if (tile >= ntiles) return;

    stage_A(sm, edge_attr, tile, E, tid);

    // prefetch B chunk 0 -> slot 0
    for (int i = tid; i < B_SLOT_BYTES / 16; i += 128)
        cpasync16(sb + SMB_B + i * 16, g_Bp + i * 16);
    CP_COMMIT();
    CP_WAIT0();
    __syncthreads();

    int q = lane & 3;
    int row0 = lane >> 2;
    // warp owns edges [w*32, w*32+32): two m16 A-tiles
    unsigned aaddr0 = sb + SMB_A +
        (unsigned)((w * 32 + (lane & 7) + ((lane >> 3) & 1) * 8) * 48 + (lane >> 4) * 16);
    unsigned aaddr1 = aaddr0 + 16 * 48;
    unsigned bext = (unsigned)((lane & 7) * 48 + ((lane & 8) ? 16 : 0)
                               + ((lane & 16) ? 384 : 0));

    int cc = 0;
    while (true) {
        unsigned a_hi0[4], a_lo0[4], a_hi1[4], a_lo1[4];
        LDMX4(a_hi0, aaddr0);
        LDMX4(a_lo0, aaddr0 + 6144);
        LDMX4(a_hi1, aaddr1);
        LDMX4(a_lo1, aaddr1 + 6144);

        int e0 = tile * 128 + w * 32 + row0;
        int e1 = e0 + 8, e2 = e0 + 16, e3 = e0 + 24;
        const float4* hp0 = (const float4*)(g_h + (size_t)((e0 < E) ? g_src[e0] : 0) * HID);
        const float4* hp1 = (const float4*)(g_h + (size_t)((e1 < E) ? g_src[e1] : 0) * HID);
        const float4* hp2 = (const float4*)(g_h + (size_t)((e2 < E) ? g_src[e2] : 0) * HID);
        const float4* hp3 = (const float4*)(g_h + (size_t)((e3 < E) ? g_src[e3] : 0) * HID);

        float msgA[16], msgB[16], msgC[16], msgD[16];
#pragma unroll
        for (int i = 0; i < 16; i++) { msgA[i] = 0.f; msgB[i] = 0.f; msgC[i] = 0.f; msgD[i] = 0.f; }

#pragma unroll 1
        for (int c = 0; c < NCHUNK; c++, cc++) {
            int slot = cc & 1;
            {   // prefetch next chunk in the tile-independent sequence
                int nc = (cc + 1) & 15;
                const unsigned char* src = g_Bp + (size_t)nc * B_SLOT_BYTES;
                unsigned dstb = sb + SMB_B + (unsigned)(((cc + 1) & 1) * B_SLOT_BYTES);
                for (int i = tid; i < B_SLOT_BYTES / 16; i += 128)
                    cpasync16(dstb + i * 16, src + i * 16);
                CP_COMMIT();
            }
            unsigned slotbase = sb + SMB_B + (unsigned)(slot * B_SLOT_BYTES);
            unsigned bhib  = slotbase + bext;
            unsigned biasb = slotbase + (unsigned)B_BIAS_OFF + (unsigned)(q * 8);
            float4 hv0 = __ldg(hp0 + c);
            float4 hv1 = __ldg(hp1 + c);
            float4 hv2 = __ldg(hp2 + c);
            float4 hv3 = __ldg(hp3 + c);
            float h0a[4] = {hv0.x, hv0.y, hv0.z, hv0.w};
            float h1a[4] = {hv1.x, hv1.y, hv1.z, hv1.w};
            float h2a[4] = {hv2.x, hv2.y, hv2.z, hv2.w};
            float h3a[4] = {hv3.x, hv3.y, hv3.z, hv3.w};
#pragma unroll
            for (int hb = 0; hb < 4; hb++) {
                float hs0 = h0a[hb], hs1 = h1a[hb], hs2 = h2a[hb], hs3 = h3a[hb];
#pragma unroll
                for (int jp = 0; jp < 4; jp++) {
                    int jj0 = hb * 8 + jp * 2;
                    unsigned bh[4];
                    LDMX4(bh, bhib + (unsigned)(jj0 * 384));
                    float bb0x, bb0y, bb1x, bb1y;
                    asm("ld.shared.v2.f32 {%0,%1},[%2];"
                        : "=f"(bb0x), "=f"(bb0y) : "r"(biasb + (unsigned)(jj0 * 32)));
                    asm("ld.shared.v2.f32 {%0,%1},[%2];"
                        : "=f"(bb1x), "=f"(bb1y) : "r"(biasb + (unsigned)(jj0 * 32 + 32)));
                    // 4 independent 2-MMA chains
                    float c0 = bb0x, c1 = bb0y, c2 = bb0x, c3 = bb0y;
                    float d0 = bb1x, d1 = bb1y, d2 = bb1x, d3 = bb1y;
                    float f0 = bb0x, f1 = bb0y, f2 = bb0x, f3 = bb0y;
                    float g0 = bb1x, g1 = bb1y, g2 = bb1x, g3 = bb1y;
                    MMA_BF16(c0, c1, c2, c3, a_hi0, bh[0], bh[1]);
                    MMA_BF16(d0, d1, d2, d3, a_hi0, bh[2], bh[3]);
                    MMA_BF16(f0, f1, f2, f3, a_hi1, bh[0], bh[1]);
                    MMA_BF16(g0, g1, g2, g3, a_hi1, bh[2], bh[3]);
                    MMA_BF16(c0, c1, c2, c3, a_lo0, bh[0], bh[1]);
                    MMA_BF16(d0, d1, d2, d3, a_lo0, bh[2], bh[3]);
                    MMA_BF16(f0, f1, f2, f3, a_lo1, bh[0], bh[1]);
                    MMA_BF16(g0, g1, g2, g3, a_lo1, bh[2], bh[3]);
                    // epilogue: relu + h-weighted accumulate
                    int m = 4 * jp;
                    msgA[m]     = fmaf(hs0, fmaxf(c0, 0.f), msgA[m]);
                    msgA[m + 1] = fmaf(hs0, fmaxf(c1, 0.f), msgA[m + 1]);
                    msgB[m]     = fmaf(hs1, fmaxf(c2, 0.f), msgB[m]);
                    msgB[m + 1] = fmaf(hs1, fmaxf(c3, 0.f), msgB[m + 1]);
                    msgA[m + 2] = fmaf(hs0, fmaxf(d0, 0.f), msgA[m + 2]);
                    msgA[m + 3] = fmaf(hs0, fmaxf(d1, 0.f), msgA[m + 3]);
                    msgB[m + 2] = fmaf(hs1, fmaxf(d2, 0.f), msgB[m + 2]);
                    msgB[m + 3] = fmaf(hs1, fmaxf(d3, 0.f), msgB[m + 3]);
                    msgC[m]     = fmaf(hs2, fmaxf(f0, 0.f), msgC[m]);
                    msgC[m + 1] = fmaf(hs2, fmaxf(f1, 0.f), msgC[m + 1]);
                    msgD[m]     = fmaf(hs3, fmaxf(f2, 0.f), msgD[m]);
                    msgD[m + 1] = fmaf(hs3, fmaxf(f3, 0.f), msgD[m + 1]);
                    msgC[m + 2] = fmaf(hs2, fmaxf(g0, 0.f), msgC[m + 2]);
                    msgC[m + 3] = fmaf(hs2, fmaxf(g1, 0.f), msgC[m + 3]);
                    msgD[m + 2] = fmaf(hs3, fmaxf(g2, 0.f), msgD[m + 2]);
                    msgD[m + 3] = fmaf(hs3, fmaxf(g3, 0.f), msgD[m + 3]);
                }
            }
            CP_WAIT0();
            __syncthreads();
        }

        // scatter: each (edge, o) has a unique owner thread
        if (e0 < E) {
            float* d = g_num + (size_t)g_dst[e0] * HID + 2 * q;
#pragma unroll
            for (int i = 0; i < 8; i++) {
                atomicAdd(d + 8 * i,     msgA[2 * i]);
                atomicAdd(d + 8 * i + 1, msgA[2 * i + 1]);
            }
        }
        if (e1 < E) {
            float* d = g_num + (size_t)g_dst[e1] * HID + 2 * q;
#pragma unroll
            for (int i = 0; i < 8; i++) {
                atomicAdd(d + 8 * i,     msgB[2 * i]);
                atomicAdd(d + 8 * i + 1, msgB[2 * i + 1]);
            }
        }
        if (e2 < E) {
            float* d = g_num + (size_t)g_dst[e2] * HID + 2 * q;
#pragma unroll
            for (int i = 0; i < 8; i++) {
                atomicAdd(d + 8 * i,     msgC[2 * i]);
                atomicAdd(d + 8 * i + 1, msgC[2 * i + 1]);
            }
        }
        if (e3 < E) {
            float* d = g_num + (size_t)g_dst[e3] * HID + 2 * q;
#pragma unroll
            for (int i = 0; i < 8; i++) {
                atomicAdd(d + 8 * i,     msgD[2 * i]);
                atomicAdd(d + 8 * i + 1, msgD[2 * i + 1]);
            }
        }

        // next tile from the ticket
        if (tid == 0) s_tile = atomicAdd(&g_ticket, 1);
        __syncthreads();
        tile = s_tile;
        if (tile >= ntiles) break;
        stage_A(sm, edge_attr, tile, E, tid);
        __syncthreads();
    }
}

// ---------------- final: relu(h@root_w + num/cnt + conv_b) -> mu/logvar -----
__global__ void __launch_bounds__(256) final_kernel(
    const float* __restrict__ root_w, const float* __restrict__ conv_b,
    const float* __restrict__ mu_w, const float* __restrict__ mu_b,
    const float* __restrict__ lv_w, const float* __restrict__ lv_b,
    float* __restrict__ out, int N) {
    __shared__ float rw[HID][HID];
    __shared__ float mw[HID][LAT];
    __shared__ float lw[HID][LAT];
    __shared__ float hv[4][HID];
    __shared__ float tv[4][HID];
    int tid = threadIdx.x;
    for (int idx = tid; idx < HID * HID / 4; idx += 256)
        ((float4*)rw)[idx] = ((const float4*)root_w)[idx];
    for (int idx = tid; idx < HID * LAT / 4; idx += 256)
        ((float4*)mw)[idx] = ((const float4*)mu_w)[idx];
    for (int idx = tid; idx < HID * LAT / 4; idx += 256)
        ((float4*)lw)[idx] = ((const float4*)lv_w)[idx];
    __syncthreads();

    int g = tid >> 6;
    int o = tid & 63;
    float cb = conv_b[o];
    float hb = (o < LAT) ? mu_b[o] : lv_b[o - LAT];

    for (int nl = g; nl < 16; nl += 4) {
        int n = blockIdx.x * 16 + nl;
        bool valid = n < N;
        if (valid) hv[g][o] = g_h[(size_t)n * HID + o];
        asm volatile("bar.sync %0, 64;" :: "r"(g + 1) : "memory");
        if (valid) {
            float inv = 1.f / fmaxf(g_cnt[n], 1.f);
            float acc = cb + g_num[(size_t)n * HID + o] * inv;
#pragma unroll
            for (int h = 0; h < HID; h++) acc += hv[g][h] * rw[h][o];
            tv[g][o] = fmaxf(acc, 0.f);
        }
        asm volatile("bar.sync %0, 64;" :: "r"(g + 1) : "memory");
        if (valid) {
            if (o < LAT) {
                float m = hb;
#pragma unroll
                for (int k = 0; k < HID; k++) m += tv[g][k] * mw[k][o];
                out[(size_t)n * LAT + o] = m;
            } else {
                int l = o - LAT;
                float m = hb;
#pragma unroll
                for (int k = 0; k < HID; k++) m += tv[g][k] * lw[k][l];
                out[(size_t)N * LAT + (size_t)n * LAT + l] = m;
            }
        }
        asm volatile("bar.sync %0, 64;" :: "r"(g + 1) : "memory");
    }
}

// ---------------- launcher ---------------------------------------------------
extern "C" void kernel_launch(void* const* d_in, const int* in_sizes, int n_in,
                              void* d_out, int out_size) {
    const float* x      = (const float*)d_in[0];
    const void*  ei     = d_in[1];
    const float* ea     = (const float*)d_in[2];
    const float* lin_w  = (const float*)d_in[3];
    const float* lin_b  = (const float*)d_in[4];
    const float* ker_w  = (const float*)d_in[5];
    const float* ker_b  = (const float*)d_in[6];
    const float* root_w = (const float*)d_in[7];
    const float* conv_b = (const float*)d_in[8];
    const float* mu_w   = (const float*)d_in[9];
    const float* mu_b   = (const float*)d_in[10];
    const float* lv_w   = (const float*)d_in[11];
    const float* lv_b   = (const float*)d_in[12];

    int N = in_sizes[0] / IN_DIM;
    int E = in_sizes[1] / 2;
    if (N > NMAX) N = NMAX;
    if (E > EMAX) E = EMAX;

    cudaFuncSetAttribute(edge_kernel, cudaFuncAttributeMaxDynamicSharedMemorySize,
                         SMEM_EDGE);

    int ntiles = (E + 127) / 128;
    int grid   = (ntiles < EDGE_GRID) ? ntiles : EDGE_GRID;

    setup_kernel<<<640, 256>>>((const int*)ei, ker_w, ker_b, N);
    convert_kernel<<<(E + 255) / 256, 256>>>(ei, E);
    hin_kernel<<<(N + 15) / 16, 128>>>(x, lin_w, lin_b, N);
    edge_kernel<<<grid, 128, SMEM_EDGE>>>(ea, E, ntiles);
    final_kernel<<<(N + 15) / 16, 256>>>(root_w, conv_b, mu_w, mu_b, lv_w, lv_b,
                                         (float*)d_out, N);
}

// round 11
// speedup vs baseline: 1.2398x; 1.0310x over previous
#include <cuda_runtime.h>
#include <cuda_bf16.h>
#include <cstdint>

// Problem constants (shapes fixed by the reference: N=20000, E=100000)
#define NMAX 20000
#define EMAX 100000
constexpr int IN_DIM = 128;
constexpr int HID    = 64;
constexpr int LAT    = 32;
constexpr int EDIM   = 16;

// ---------------- edge kernel geometry --------------------------------------
// 256 threads = 8 warps; 128 edges per tile; warp w owns 16 edges (one m16
// A-tile). 2-term bf16 split: W ~= (ahi + alo) * bf16(B). Persistent CTAs
// (grid = 444 = 148 SMs * 3 CTAs) pull tiles from a global ticket; B cp.async
// double-buffer runs continuously across tile boundaries.
constexpr int B_CHUNK_BYTES = 256 * 48;          // bh image: 12288
constexpr int B_BIAS_OFF    = B_CHUNK_BYTES;     // 12288
constexpr int B_SLOT_BYTES  = B_BIAS_OFF + 1024; // bh + bias: 13312
constexpr int NCHUNK        = 16;
constexpr int EDGE_GRID     = 444;

// dynamic smem layout (16B aligned blocks). No H stage (h read via LDG from L2).
constexpr int SMB_A    = 0;                       // 2 terms * 128*48 = 12288
constexpr int SMB_B    = 12288;                   // 2 slots * 13312 = 26624
constexpr int SMEM_EDGE = SMB_B + 2 * B_SLOT_BYTES;   // 38912 (3 CTAs/SM)

// ---------------- scratch (device globals; no cudaMalloc allowed) -----------
__device__ float g_h[NMAX * HID];
__device__ float g_num[NMAX * HID];
__device__ float g_cnt[NMAX];
__device__ int   g_src[EMAX];
__device__ int   g_dst[EMAX];
__device__ int   g_is64;
__device__ int   g_ticket;
__device__ __align__(16) unsigned char g_Bp[NCHUNK * B_SLOT_BYTES]; // 208KB

// ---------------- helpers ----------------------------------------------------
typedef unsigned long long u64;

__device__ __forceinline__ u64 pk2(float x, float y) {
    u64 r; asm("mov.b64 %0,{%1,%2};" : "=l"(r) : "f"(x), "f"(y)); return r;
}
__device__ __forceinline__ void upk2(u64 v, float& x, float& y) {
    asm("mov.b64 {%0,%1},%2;" : "=f"(x), "=f"(y) : "l"(v));
}
__device__ __forceinline__ u64 ffma2(u64 a, u64 b, u64 c) {
    u64 d; asm("fma.rn.f32x2 %0,%1,%2,%3;" : "=l"(d) : "l"(a), "l"(b), "l"(c)); return d;
}
__device__ __forceinline__ unsigned smem_u32(const void* p) {
    return (unsigned)__cvta_generic_to_shared(p);
}
__device__ __forceinline__ void cpasync16(unsigned dst, const void* src) {
    asm volatile("cp.async.ca.shared.global [%0], [%1], 16;" :: "r"(dst), "l"(src));
}
#define CP_COMMIT() asm volatile("cp.async.commit_group;" ::: "memory")
#define CP_WAIT0()  asm volatile("cp.async.wait_group 0;" ::: "memory")

#define LDMX4(r, addr) \
    asm volatile("ldmatrix.sync.aligned.m8n8.x4.shared.b16 {%0,%1,%2,%3},[%4];" \
                 : "=r"((r)[0]), "=r"((r)[1]), "=r"((r)[2]), "=r"((r)[3]) : "r"(addr))

#define MMA_BF16(c0, c1, c2, c3, a, b0, b1) \
    asm volatile("mma.sync.aligned.m16n8k16.row.col.f32.bf16.bf16.f32 " \
                 "{%0,%1,%2,%3},{%4,%5,%6,%7},{%8,%9},{%0,%1,%2,%3};" \
                 : "+f"(c0), "+f"(c1), "+f"(c2), "+f"(c3) \
                 : "r"((a)[0]), "r"((a)[1]), "r"((a)[2]), "r"((a)[3]), \
                   "r"(b0), "r"(b1))

// ---------------- setup: detect + zero + prep + ticket reset -----------------
__global__ void setup_kernel(const int* __restrict__ ei,
                             const float* __restrict__ kw,
                             const float* __restrict__ kb, int N) {
    int gtid = blockIdx.x * 256 + threadIdx.x;
    int gsz  = gridDim.x * 256;
    if (gtid == 0) {
        int is64 = 1;
#pragma unroll
        for (int k = 0; k < 32; k++)
            if (ei[2 * k + 1] != 0) is64 = 0;
        g_is64 = is64;
        g_ticket = 0;
    }
    int tot = N * HID;
    for (int i = gtid; i < tot; i += gsz) g_num[i] = 0.f;
    for (int j = gtid; j < N; j += gsz)   g_cnt[j] = 0.f;
    // prep B image: bf16(round-nearest) with 48B row stride (pad stays 0-init)
    for (int idx = gtid; idx < 4096 * 16; idx += gsz) {
        int n = idx >> 4, k = idx & 15;
        float v = kw[(size_t)k * 4096 + n];
        int c = n >> 8, nl = n & 255;
        *(__nv_bfloat16*)(g_Bp + (size_t)c * B_SLOT_BYTES + (size_t)nl * 48
                          + (size_t)k * 2) = __float2bfloat16_rn(v);
    }
    for (int n = gtid; n < 4096; n += gsz) {
        int c = n >> 8, nl = n & 255;
        *(float*)(g_Bp + (size_t)c * B_SLOT_BYTES + B_BIAS_OFF + (size_t)nl * 4) = kb[n];
    }
}

__global__ void convert_kernel(const void* __restrict__ ei, int E) {
    int e = blockIdx.x * blockDim.x + threadIdx.x;
    if (e >= E) return;
    int s, d;
    if (g_is64) {
        const long long* p = (const long long*)ei;
        s = (int)p[e]; d = (int)p[E + e];
    } else {
        const int* p = (const int*)ei;
        s = p[e]; d = p[E + e];
    }
    g_src[e] = s; g_dst[e] = d;
    atomicAdd(&g_cnt[d], 1.f);
}

// ---------------- h = relu(x @ lin_in_w + lin_in_b) -------------------------
__global__ void __launch_bounds__(128) hin_kernel(
    const float* __restrict__ x, const float* __restrict__ w,
    const float* __restrict__ b, int N) {
    __shared__ u64   ws2[IN_DIM][32];   // (w[d][2p], w[d][2p+1])
    __shared__ float xs[16][IN_DIM];
    int tid = threadIdx.x;
    for (int i = tid; i < IN_DIM * 32; i += 128)
        ((u64*)ws2)[i] = ((const u64*)w)[i];
    int base = blockIdx.x * 16;
    for (int i = tid; i < 16 * 32; i += 128) {
        int nl = i >> 5, j = i & 31;
        int n = base + nl;
        if (n < N) ((float4*)xs[nl])[j] = ((const float4*)(x + (size_t)n * IN_DIM))[j];
    }
    __syncthreads();
    int p = tid & 31, g = tid >> 5;
    float2 b2 = ((const float2*)b)[p];
    u64 bias2 = pk2(b2.x, b2.y);
    u64 acc0 = bias2, acc1 = bias2, acc2 = bias2, acc3 = bias2;
#pragma unroll 8
    for (int d = 0; d < IN_DIM; d++) {
        u64 w2 = ws2[d][p];
        acc0 = ffma2(pk2(xs[g][d],      xs[g][d]),      w2, acc0);
        acc1 = ffma2(pk2(xs[g + 4][d],  xs[g + 4][d]),  w2, acc1);
        acc2 = ffma2(pk2(xs[g + 8][d],  xs[g + 8][d]),  w2, acc2);
        acc3 = ffma2(pk2(xs[g + 12][d], xs[g + 12][d]), w2, acc3);
    }
    u64 accs[4] = {acc0, acc1, acc2, acc3};
#pragma unroll
    for (int q = 0; q < 4; q++) {
        int n = base + g + 4 * q;
        if (n < N) {
            float v0, v1; upk2(accs[q], v0, v1);
            float2 r; r.x = fmaxf(v0, 0.f); r.y = fmaxf(v1, 0.f);
            *(float2*)(g_h + (size_t)n * HID + 2 * p) = r;
        }
    }
}

// ---------------- fused edge kernel (mma.sync bf16 2-term, persistent) -------
__device__ __forceinline__ void stage_A(unsigned char* sm,
                                        const float* __restrict__ edge_attr,
                                        int tile, int E, int tid) {
    if (tid >= 128) return;
    int e = tile * 128 + tid;
    float va[16];
    if (e < E) {
        const float4* p = (const float4*)(edge_attr + (size_t)e * EDIM);
#pragma unroll
        for (int i = 0; i < 4; i++) {
            float4 q4 = p[i];
            va[4*i] = q4.x; va[4*i+1] = q4.y; va[4*i+2] = q4.z; va[4*i+3] = q4.w;
        }
    } else {
#pragma unroll
        for (int i = 0; i < 16; i++) va[i] = 0.f;
    }
#pragma unroll
    for (int k = 0; k < 8; k++) {
        float v0 = va[2*k], v1 = va[2*k+1];
        __nv_bfloat16 h0 = __float2bfloat16_rn(v0);
        __nv_bfloat16 h1 = __float2bfloat16_rn(v1);
        __nv_bfloat162 hp; hp.x = h0; hp.y = h1;
        __nv_bfloat162 lp;
        lp.x = __float2bfloat16_rn(v0 - __bfloat162float(h0));
        lp.y = __float2bfloat16_rn(v1 - __bfloat162float(h1));
        *(__nv_bfloat162*)(sm + SMB_A + tid * 48 + k * 4)        = hp;
        *(__nv_bfloat162*)(sm + SMB_A + 6144 + tid * 48 + k * 4) = lp;
    }
}

__global__ void __launch_bounds__(256, 3) edge_kernel(
    const float* __restrict__ edge_attr, int E, int ntiles) {
    extern __shared__ __align__(16) unsigned char sm[];
    __shared__ int s_tile;
    unsigned sb = smem_u32(sm);
    int tid = threadIdx.x, lane = tid & 31, w = tid >> 5;

    if (tid == 0) s_tile = atomicAdd(&g_ticket, 1);
    __syncthreads();
    int tile = s_tile;
    if (tile >= ntiles) return;

    stage_A(sm, edge_attr, tile, E, tid);

    // prefetch B chunk 0 -> slot 0
    for (int i = tid; i < B_SLOT_BYTES / 16; i += 256)
        cpasync16(sb + SMB_B + i * 16, g_Bp + i * 16);
    CP_COMMIT();
    CP_WAIT0();
    __syncthreads();

    int q = lane & 3;
    int row0 = lane >> 2;
    // warp owns edges [w*16, w*16+16): one m16 A-tile
    unsigned aaddr0 = sb + SMB_A +
        (unsigned)((w * 16 + (lane & 7) + ((lane >> 3) & 1) * 8) * 48 + (lane >> 4) * 16);
    unsigned bext = (unsigned)((lane & 7) * 48 + ((lane & 8) ? 16 : 0)
                               + ((lane & 16) ? 384 : 0));

    int cc = 0;
    while (true) {
        unsigned a_hi[4], a_lo[4];
        LDMX4(a_hi, aaddr0);
        LDMX4(a_lo, aaddr0 + 6144);

        int e0 = tile * 128 + w * 16 + row0;
        int e1 = e0 + 8;
        const float4* hp0 = (const float4*)(g_h + (size_t)((e0 < E) ? g_src[e0] : 0) * HID);
        const float4* hp1 = (const float4*)(g_h + (size_t)((e1 < E) ? g_src[e1] : 0) * HID);

        float msgA[16], msgB[16];
#pragma unroll
        for (int i = 0; i < 16; i++) { msgA[i] = 0.f; msgB[i] = 0.f; }

#pragma unroll 1
        for (int c = 0; c < NCHUNK; c++, cc++) {
            int slot = cc & 1;
            {   // prefetch next chunk in the tile-independent sequence
                int nc = (cc + 1) & 15;
                const unsigned char* src = g_Bp + (size_t)nc * B_SLOT_BYTES;
                unsigned dstb = sb + SMB_B + (unsigned)(((cc + 1) & 1) * B_SLOT_BYTES);
                for (int i = tid; i < B_SLOT_BYTES / 16; i += 256)
                    cpasync16(dstb + i * 16, src + i * 16);
                CP_COMMIT();
            }
            unsigned slotbase = sb + SMB_B + (unsigned)(slot * B_SLOT_BYTES);
            unsigned bhib  = slotbase + bext;
            unsigned biasb = slotbase + (unsigned)B_BIAS_OFF + (unsigned)(q * 8);
            float4 hv0 = __ldg(hp0 + c);
            float4 hv1 = __ldg(hp1 + c);
            float h0a[4] = {hv0.x, hv0.y, hv0.z, hv0.w};
            float h1a[4] = {hv1.x, hv1.y, hv1.z, hv1.w};
#pragma unroll
            for (int hb = 0; hb < 4; hb++) {
                float hs0 = h0a[hb], hs1 = h1a[hb];
#pragma unroll
                for (int jp = 0; jp < 4; jp++) {
                    int jj0 = hb * 8 + jp * 2;
                    unsigned bh[4];
                    LDMX4(bh, bhib + (unsigned)(jj0 * 384));
                    float bb0x, bb0y, bb1x, bb1y;
                    asm("ld.shared.v2.f32 {%0,%1},[%2];"
                        : "=f"(bb0x), "=f"(bb0y) : "r"(biasb + (unsigned)(jj0 * 32)));
                    asm("ld.shared.v2.f32 {%0,%1},[%2];"
                        : "=f"(bb1x), "=f"(bb1y) : "r"(biasb + (unsigned)(jj0 * 32 + 32)));
                    // 2 independent 2-MMA chains (jj0, jj1)
                    float c0 = bb0x, c1 = bb0y, c2 = bb0x, c3 = bb0y;
                    float d0 = bb1x, d1 = bb1y, d2 = bb1x, d3 = bb1y;
                    MMA_BF16(c0, c1, c2, c3, a_hi, bh[0], bh[1]);
                    MMA_BF16(d0, d1, d2, d3, a_hi, bh[2], bh[3]);
                    MMA_BF16(c0, c1, c2, c3, a_lo, bh[0], bh[1]);
                    MMA_BF16(d0, d1, d2, d3, a_lo, bh[2], bh[3]);
                    // epilogue: relu + h-weighted accumulate
                    int m = 4 * jp;
                    msgA[m]     = fmaf(hs0, fmaxf(c0, 0.f), msgA[m]);
                    msgA[m + 1] = fmaf(hs0, fmaxf(c1, 0.f), msgA[m + 1]);
                    msgB[m]     = fmaf(hs1, fmaxf(c2, 0.f), msgB[m]);
                    msgB[m + 1] = fmaf(hs1, fmaxf(c3, 0.f), msgB[m + 1]);
                    msgA[m + 2] = fmaf(hs0, fmaxf(d0, 0.f), msgA[m + 2]);
                    msgA[m + 3] = fmaf(hs0, fmaxf(d1, 0.f), msgA[m + 3]);
                    msgB[m + 2] = fmaf(hs1, fmaxf(d2, 0.f), msgB[m + 2]);
                    msgB[m + 3] = fmaf(hs1, fmaxf(d3, 0.f), msgB[m + 3]);
                }
            }
            CP_WAIT0();
            __syncthreads();
        }

        // scatter: each (edge, o) has a unique owner thread
        if (e0 < E) {
            float* d = g_num + (size_t)g_dst[e0] * HID + 2 * q;
#pragma unroll
            for (int i = 0; i < 8; i++) {
                atomicAdd(d + 8 * i,     msgA[2 * i]);
                atomicAdd(d + 8 * i + 1, msgA[2 * i + 1]);
            }
        }
        if (e1 < E) {
            float* d = g_num + (size_t)g_dst[e1] * HID + 2 * q;
#pragma unroll
            for (int i = 0; i < 8; i++) {
                atomicAdd(d + 8 * i,     msgB[2 * i]);
                atomicAdd(d + 8 * i + 1, msgB[2 * i + 1]);
            }
        }

        // next tile from the ticket
        if (tid == 0) s_tile = atomicAdd(&g_ticket, 1);
        __syncthreads();
        tile = s_tile;
        if (tile >= ntiles) break;
        stage_A(sm, edge_attr, tile, E, tid);
        __syncthreads();
    }
}

// ---------------- final: relu(h@root_w + num/cnt + conv_b) -> mu/logvar -----
__global__ void __launch_bounds__(256) final_kernel(
    const float* __restrict__ root_w, const float* __restrict__ conv_b,
    const float* __restrict__ mu_w, const float* __restrict__ mu_b,
    const float* __restrict__ lv_w, const float* __restrict__ lv_b,
    float* __restrict__ out, int N) {
    __shared__ float rw[HID][HID];
    __shared__ float mw[HID][LAT];
    __shared__ float lw[HID][LAT];
    __shared__ float hv[4][HID];
    __shared__ float tv[4][HID];
    int tid = threadIdx.x;
    for (int idx = tid; idx < HID * HID / 4; idx += 256)
        ((float4*)rw)[idx] = ((const float4*)root_w)[idx];
    for (int idx = tid; idx < HID * LAT / 4; idx += 256)
        ((float4*)mw)[idx] = ((const float4*)mu_w)[idx];
    for (int idx = tid; idx < HID * LAT / 4; idx += 256)
        ((float4*)lw)[idx] = ((const float4*)lv_w)[idx];
    __syncthreads();

    int g = tid >> 6;
    int o = tid & 63;
    float cb = conv_b[o];
    float hb = (o < LAT) ? mu_b[o] : lv_b[o - LAT];

    for (int nl = g; nl < 16; nl += 4) {
        int n = blockIdx.x * 16 + nl;
        bool valid = n < N;
        if (valid) hv[g][o] = g_h[(size_t)n * HID + o];
        asm volatile("bar.sync %0, 64;" :: "r"(g + 1) : "memory");
        if (valid) {
            float inv = 1.f / fmaxf(g_cnt[n], 1.f);
            float acc = cb + g_num[(size_t)n * HID + o] * inv;
#pragma unroll
            for (int h = 0; h < HID; h++) acc += hv[g][h] * rw[h][o];
            tv[g][o] = fmaxf(acc, 0.f);
        }
        asm volatile("bar.sync %0, 64;" :: "r"(g + 1) : "memory");
        if (valid) {
            if (o < LAT) {
                float m = hb;
#pragma unroll
                for (int k = 0; k < HID; k++) m += tv[g][k] * mw[k][o];
                out[(size_t)n * LAT + o] = m;
            } else {
                int l = o - LAT;
                float m = hb;
#pragma unroll
                for (int k = 0; k < HID; k++) m += tv[g][k] * lw[k][l];
                out[(size_t)N * LAT + (size_t)n * LAT + l] = m;
            }
        }
        asm volatile("bar.sync %0, 64;" :: "r"(g + 1) : "memory");
    }
}

// ---------------- launcher ---------------------------------------------------
extern "C" void kernel_launch(void* const* d_in, const int* in_sizes, int n_in,
                              void* d_out, int out_size) {
    const float* x      = (const float*)d_in[0];
    const void*  ei     = d_in[1];
    const float* ea     = (const float*)d_in[2];
    const float* lin_w  = (const float*)d_in[3];
    const float* lin_b  = (const float*)d_in[4];
    const float* ker_w  = (const float*)d_in[5];
    const float* ker_b  = (const float*)d_in[6];
    const float* root_w = (const float*)d_in[7];
    const float* conv_b = (const float*)d_in[8];
    const float* mu_w   = (const float*)d_in[9];
    const float* mu_b   = (const float*)d_in[10];
    const float* lv_w   = (const float*)d_in[11];
    const float* lv_b   = (const float*)d_in[12];

    int N = in_sizes[0] / IN_DIM;
    int E = in_sizes[1] / 2;
    if (N > NMAX) N = NMAX;
    if (E > EMAX) E = EMAX;

    cudaFuncSetAttribute(edge_kernel, cudaFuncAttributeMaxDynamicSharedMemorySize,
                         SMEM_EDGE);

    int ntiles = (E + 127) / 128;
    int grid   = (ntiles < EDGE_GRID) ? ntiles : EDGE_GRID;

    setup_kernel<<<640, 256>>>((const int*)ei, ker_w, ker_b, N);
    convert_kernel<<<(E + 255) / 256, 256>>>(ei, E);
    hin_kernel<<<(N + 15) / 16, 128>>>(x, lin_w, lin_b, N);
    edge_kernel<<<grid, 256, SMEM_EDGE>>>(ea, E, ntiles);
    final_kernel<<<(N + 15) / 16, 256>>>(root_w, conv_b, mu_w, mu_b, lv_w, lv_b,
                                         (float*)d_out, N);
}

// round 12
// speedup vs baseline: 1.2592x; 1.0156x over previous
#include <cuda_runtime.h>
#include <cuda_bf16.h>
#include <cstdint>

// Problem constants (shapes fixed by the reference: N=20000, E=100000)
#define NMAX 20000
#define EMAX 100000
constexpr int IN_DIM = 128;
constexpr int HID    = 64;
constexpr int LAT    = 32;
constexpr int EDIM   = 16;

// ---------------- edge kernel geometry --------------------------------------
// 256 threads = 8 warps; 128 edges per tile; warp w owns 16 edges (one m16
// A-tile). 2-term bf16 split: W ~= (ahi + alo) * bf16(B). Persistent CTAs
// (grid = 444) pull tiles from a global ticket; B cp.async double-buffer runs
// continuously across tile boundaries. Epilogue uses packed fma.rn.f32x2.
constexpr int B_CHUNK_BYTES = 256 * 48;          // bh image: 12288
constexpr int B_BIAS_OFF    = B_CHUNK_BYTES;     // 12288
constexpr int B_SLOT_BYTES  = B_BIAS_OFF + 1024; // bh + bias: 13312
constexpr int NCHUNK        = 16;
constexpr int EDGE_GRID     = 444;

// dynamic smem layout (16B aligned blocks). No H stage (h read via LDG from L2).
constexpr int SMB_A    = 0;                       // 2 terms * 128*48 = 12288
constexpr int SMB_B    = 12288;                   // 2 slots * 13312 = 26624
constexpr int SMEM_EDGE = SMB_B + 2 * B_SLOT_BYTES;   // 38912 (3 CTAs/SM)

// ---------------- scratch (device globals; no cudaMalloc allowed) -----------
__device__ float g_h[NMAX * HID];
__device__ float g_num[NMAX * HID];
__device__ float g_cnt[NMAX];
__device__ int   g_src[EMAX];
__device__ int   g_dst[EMAX];
__device__ int   g_is64;
__device__ int   g_ticket;
__device__ __align__(16) unsigned char g_Bp[NCHUNK * B_SLOT_BYTES]; // 208KB

// ---------------- helpers ----------------------------------------------------
typedef unsigned long long u64;

__device__ __forceinline__ u64 pk2(float x, float y) {
    u64 r; asm("mov.b64 %0,{%1,%2};" : "=l"(r) : "f"(x), "f"(y)); return r;
}
__device__ __forceinline__ void upk2(u64 v, float& x, float& y) {
    asm("mov.b64 {%0,%1},%2;" : "=f"(x), "=f"(y) : "l"(v));
}
__device__ __forceinline__ u64 ffma2(u64 a, u64 b, u64 c) {
    u64 d; asm("fma.rn.f32x2 %0,%1,%2,%3;" : "=l"(d) : "l"(a), "l"(b), "l"(c)); return d;
}
__device__ __forceinline__ unsigned smem_u32(const void* p) {
    return (unsigned)__cvta_generic_to_shared(p);
}
__device__ __forceinline__ void cpasync16(unsigned dst, const void* src) {
    asm volatile("cp.async.ca.shared.global [%0], [%1], 16;" :: "r"(dst), "l"(src));
}
#define CP_COMMIT() asm volatile("cp.async.commit_group;" ::: "memory")
#define CP_WAIT0()  asm volatile("cp.async.wait_group 0;" ::: "memory")

#define LDMX4(r, addr) \
    asm volatile("ldmatrix.sync.aligned.m8n8.x4.shared.b16 {%0,%1,%2,%3},[%4];" \
                 : "=r"((r)[0]), "=r"((r)[1]), "=r"((r)[2]), "=r"((r)[3]) : "r"(addr))

#define MMA_BF16(c0, c1, c2, c3, a, b0, b1) \
    asm volatile("mma.sync.aligned.m16n8k16.row.col.f32.bf16.bf16.f32 " \
                 "{%0,%1,%2,%3},{%4,%5,%6,%7},{%8,%9},{%0,%1,%2,%3};" \
                 : "+f"(c0), "+f"(c1), "+f"(c2), "+f"(c3) \
                 : "r"((a)[0]), "r"((a)[1]), "r"((a)[2]), "r"((a)[3]), \
                   "r"(b0), "r"(b1))

// ---------------- setup: detect + zero + prep + ticket reset -----------------
__global__ void setup_kernel(const int* __restrict__ ei,
                             const float* __restrict__ kw,
                             const float* __restrict__ kb, int N) {
    int gtid = blockIdx.x * 256 + threadIdx.x;
    int gsz  = gridDim.x * 256;
    if (gtid == 0) {
        int is64 = 1;
#pragma unroll
        for (int k = 0; k < 32; k++)
            if (ei[2 * k + 1] != 0) is64 = 0;
        g_is64 = is64;
        g_ticket = 0;
    }
    int tot = N * HID;
    for (int i = gtid; i < tot; i += gsz) g_num[i] = 0.f;
    for (int j = gtid; j < N; j += gsz)   g_cnt[j] = 0.f;
    // prep B image: bf16(round-nearest) with 48B row stride (pad stays 0-init)
    for (int idx = gtid; idx < 4096 * 16; idx += gsz) {
        int n = idx >> 4, k = idx & 15;
        float v = kw[(size_t)k * 4096 + n];
        int c = n >> 8, nl = n & 255;
        *(__nv_bfloat16*)(g_Bp + (size_t)c * B_SLOT_BYTES + (size_t)nl * 48
                          + (size_t)k * 2) = __float2bfloat16_rn(v);
    }
    // bias arranged for one LDS.v4 per jp: [pairidx(16)][q(4)] -> 4 floats
    // {b(jj0,2q), b(jj0,2q+1), b(jj1,2q), b(jj1,2q+1)}
    for (int n = gtid; n < 4096; n += gsz) {
        int c = n >> 8, nl = n & 255;
        int jj = nl >> 3, col8 = nl & 7;
        int q = col8 >> 1, lo = col8 & 1;
        int pairidx = jj >> 1, odd = jj & 1;
        size_t off = (size_t)pairidx * 64 + (size_t)q * 16 + (size_t)odd * 8
                   + (size_t)lo * 4;
        *(float*)(g_Bp + (size_t)c * B_SLOT_BYTES + B_BIAS_OFF + off) = kb[n];
    }
}

__global__ void convert_kernel(const void* __restrict__ ei, int E) {
    int e = blockIdx.x * blockDim.x + threadIdx.x;
    if (e >= E) return;
    int s, d;
    if (g_is64) {
        const long long* p = (const long long*)ei;
        s = (int)p[e]; d = (int)p[E + e];
    } else {
        const int* p = (const int*)ei;
        s = p[e]; d = p[E + e];
    }
    g_src[e] = s; g_dst[e] = d;
    atomicAdd(&g_cnt[d], 1.f);
}

// ---------------- h = relu(x @ lin_in_w + lin_in_b) -------------------------
__global__ void __launch_bounds__(128) hin_kernel(
    const float* __restrict__ x, const float* __restrict__ w,
    const float* __restrict__ b, int N) {
    __shared__ u64   ws2[IN_DIM][32];   // (w[d][2p], w[d][2p+1])
    __shared__ float xs[16][IN_DIM];
    int tid = threadIdx.x;
    for (int i = tid; i < IN_DIM * 32; i += 128)
        ((u64*)ws2)[i] = ((const u64*)w)[i];
    int base = blockIdx.x * 16;
    for (int i = tid; i < 16 * 32; i += 128) {
        int nl = i >> 5, j = i & 31;
        int n = base + nl;
        if (n < N) ((float4*)xs[nl])[j] = ((const float4*)(x + (size_t)n * IN_DIM))[j];
    }
    __syncthreads();
    int p = tid & 31, g = tid >> 5;
    float2 b2 = ((const float2*)b)[p];
    u64 bias2 = pk2(b2.x, b2.y);
    u64 acc0 = bias2, acc1 = bias2, acc2 = bias2, acc3 = bias2;
#pragma unroll 8
    for (int d = 0; d < IN_DIM; d++) {
        u64 w2 = ws2[d][p];
        acc0 = ffma2(pk2(xs[g][d],      xs[g][d]),      w2, acc0);
        acc1 = ffma2(pk2(xs[g + 4][d],  xs[g + 4][d]),  w2, acc1);
        acc2 = ffma2(pk2(xs[g + 8][d],  xs[g + 8][d]),  w2, acc2);
        acc3 = ffma2(pk2(xs[g + 12][d], xs[g + 12][d]), w2, acc3);
    }
    u64 accs[4] = {acc0, acc1, acc2, acc3};
#pragma unroll
    for (int q = 0; q < 4; q++) {
        int n = base + g + 4 * q;
        if (n < N) {
            float v0, v1; upk2(accs[q], v0, v1);
            float2 r; r.x = fmaxf(v0, 0.f); r.y = fmaxf(v1, 0.f);
            *(float2*)(g_h + (size_t)n * HID + 2 * p) = r;
        }
    }
}

// ---------------- fused edge kernel (mma.sync bf16 2-term, persistent) -------
__device__ __forceinline__ void stage_A(unsigned char* sm,
                                        const float* __restrict__ edge_attr,
                                        int tile, int E, int tid) {
    if (tid >= 128) return;
    int e = tile * 128 + tid;
    float va[16];
    if (e < E) {
        const float4* p = (const float4*)(edge_attr + (size_t)e * EDIM);
#pragma unroll
        for (int i = 0; i < 4; i++) {
            float4 q4 = p[i];
            va[4*i] = q4.x; va[4*i+1] = q4.y; va[4*i+2] = q4.z; va[4*i+3] = q4.w;
        }
    } else {
#pragma unroll
        for (int i = 0; i < 16; i++) va[i] = 0.f;
    }
#pragma unroll
    for (int k = 0; k < 8; k++) {
        float v0 = va[2*k], v1 = va[2*k+1];
        __nv_bfloat16 h0 = __float2bfloat16_rn(v0);
        __nv_bfloat16 h1 = __float2bfloat16_rn(v1);
        __nv_bfloat162 hp; hp.x = h0; hp.y = h1;
        __nv_bfloat162 lp;
        lp.x = __float2bfloat16_rn(v0 - __bfloat162float(h0));
        lp.y = __float2bfloat16_rn(v1 - __bfloat162float(h1));
        *(__nv_bfloat162*)(sm + SMB_A + tid * 48 + k * 4)        = hp;
        *(__nv_bfloat162*)(sm + SMB_A + 6144 + tid * 48 + k * 4) = lp;
    }
}

__global__ void __launch_bounds__(256, 3) edge_kernel(
    const float* __restrict__ edge_attr, int E, int ntiles) {
    extern __shared__ __align__(16) unsigned char sm[];
    __shared__ int s_tile;
    unsigned sb = smem_u32(sm);
    int tid = threadIdx.x, lane = tid & 31, w = tid >> 5;

    if (tid == 0) s_tile = atomicAdd(&g_ticket, 1);
    __syncthreads();
    int tile = s_tile;
    if (tile >= ntiles) return;

    stage_A(sm, edge_attr, tile, E, tid);

    // prefetch B chunk 0 -> slot 0
    for (int i = tid; i < B_SLOT_BYTES / 16; i += 256)
        cpasync16(sb + SMB_B + i * 16, g_Bp + i * 16);
    CP_COMMIT();
    CP_WAIT0();
    __syncthreads();

    int q = lane & 3;
    int row0 = lane >> 2;
    // warp owns edges [w*16, w*16+16): one m16 A-tile
    unsigned aaddr0 = sb + SMB_A +
        (unsigned)((w * 16 + (lane & 7) + ((lane >> 3) & 1) * 8) * 48 + (lane >> 4) * 16);
    unsigned bext = (unsigned)((lane & 7) * 48 + ((lane & 8) ? 16 : 0)
                               + ((lane & 16) ? 384 : 0));

    int cc = 0;
    while (true) {
        unsigned a_hi[4], a_lo[4];
        LDMX4(a_hi, aaddr0);
        LDMX4(a_lo, aaddr0 + 6144);

        int e0 = tile * 128 + w * 16 + row0;
        int e1 = e0 + 8;
        const float4* hp0 = (const float4*)(g_h + (size_t)((e0 < E) ? g_src[e0] : 0) * HID);
        const float4* hp1 = (const float4*)(g_h + (size_t)((e1 < E) ? g_src[e1] : 0) * HID);

        u64 msgA2[8], msgB2[8];      // packed f32x2 accumulators
#pragma unroll
        for (int i = 0; i < 8; i++) { msgA2[i] = 0ULL; msgB2[i] = 0ULL; }

#pragma unroll 1
        for (int c = 0; c < NCHUNK; c++, cc++) {
            int slot = cc & 1;
            {   // prefetch next chunk in the tile-independent sequence
                int nc = (cc + 1) & 15;
                const unsigned char* src = g_Bp + (size_t)nc * B_SLOT_BYTES;
                unsigned dstb = sb + SMB_B + (unsigned)(((cc + 1) & 1) * B_SLOT_BYTES);
                for (int i = tid; i < B_SLOT_BYTES / 16; i += 256)
                    cpasync16(dstb + i * 16, src + i * 16);
                CP_COMMIT();
            }
            unsigned slotbase = sb + SMB_B + (unsigned)(slot * B_SLOT_BYTES);
            unsigned bhib  = slotbase + bext;
            unsigned biasb = slotbase + (unsigned)B_BIAS_OFF + (unsigned)(q * 16);
            float4 hv0 = __ldg(hp0 + c);
            float4 hv1 = __ldg(hp1 + c);
            float h0a[4] = {hv0.x, hv0.y, hv0.z, hv0.w};
            float h1a[4] = {hv1.x, hv1.y, hv1.z, hv1.w};
#pragma unroll
            for (int hb = 0; hb < 4; hb++) {
                u64 h2a = pk2(h0a[hb], h0a[hb]);
                u64 h2b = pk2(h1a[hb], h1a[hb]);
#pragma unroll
                for (int jp = 0; jp < 4; jp++) {
                    int jj0 = hb * 8 + jp * 2;
                    unsigned bh[4];
                    LDMX4(bh, bhib + (unsigned)(jj0 * 384));
                    // one LDS.v4: C-inits for (jj0 pair, jj1 pair)
                    float bx, by, bz, bw;
                    asm("ld.shared.v4.f32 {%0,%1,%2,%3},[%4];"
                        : "=f"(bx), "=f"(by), "=f"(bz), "=f"(bw)
                        : "r"(biasb + (unsigned)((hb * 4 + jp) * 64)));
                    // 2 independent 2-MMA chains (jj0, jj1)
                    float c0 = bx, c1 = by, c2 = bx, c3 = by;
                    float d0 = bz, d1 = bw, d2 = bz, d3 = bw;
                    MMA_BF16(c0, c1, c2, c3, a_hi, bh[0], bh[1]);
                    MMA_BF16(d0, d1, d2, d3, a_hi, bh[2], bh[3]);
                    MMA_BF16(c0, c1, c2, c3, a_lo, bh[0], bh[1]);
                    MMA_BF16(d0, d1, d2, d3, a_lo, bh[2], bh[3]);
                    // epilogue: scalar relu + packed h-weighted accumulate
                    float r0 = fmaxf(c0, 0.f), r1 = fmaxf(c1, 0.f);
                    float r2 = fmaxf(c2, 0.f), r3 = fmaxf(c3, 0.f);
                    float s0 = fmaxf(d0, 0.f), s1 = fmaxf(d1, 0.f);
                    float s2 = fmaxf(d2, 0.f), s3 = fmaxf(d3, 0.f);
                    msgA2[2*jp]     = ffma2(h2a, pk2(r0, r1), msgA2[2*jp]);
                    msgB2[2*jp]     = ffma2(h2b, pk2(r2, r3), msgB2[2*jp]);
                    msgA2[2*jp + 1] = ffma2(h2a, pk2(s0, s1), msgA2[2*jp + 1]);
                    msgB2[2*jp + 1] = ffma2(h2b, pk2(s2, s3), msgB2[2*jp + 1]);
                }
            }
            CP_WAIT0();
            __syncthreads();
        }

        // scatter: each (edge, o) has a unique owner thread; msgX2[i] <-> o = 8i + 2q
        if (e0 < E) {
            float* d = g_num + (size_t)g_dst[e0] * HID + 2 * q;
#pragma unroll
            for (int i = 0; i < 8; i++) {
                float v0, v1; upk2(msgA2[i], v0, v1);
                atomicAdd(d + 8 * i,     v0);
                atomicAdd(d + 8 * i + 1, v1);
            }
        }
        if (e1 < E) {
            float* d = g_num + (size_t)g_dst[e1] * HID + 2 * q;
#pragma unroll
            for (int i = 0; i < 8; i++) {
                float v0, v1; upk2(msgB2[i], v0, v1);
                atomicAdd(d + 8 * i,     v0);
                atomicAdd(d + 8 * i + 1, v1);
            }
        }

        // next tile from the ticket
        if (tid == 0) s_tile = atomicAdd(&g_ticket, 1);
        __syncthreads();
        tile = s_tile;
        if (tile >= ntiles) break;
        stage_A(sm, edge_attr, tile, E, tid);
        __syncthreads();
    }
}

// ---------------- final: relu(h@root_w + num/cnt + conv_b) -> mu/logvar -----
__global__ void __launch_bounds__(256) final_kernel(
    const float* __restrict__ root_w, const float* __restrict__ conv_b,
    const float* __restrict__ mu_w, const float* __restrict__ mu_b,
    const float* __restrict__ lv_w, const float* __restrict__ lv_b,
    float* __restrict__ out, int N) {
    __shared__ float rw[HID][HID];
    __shared__ float mw[HID][LAT];
    __shared__ float lw[HID][LAT];
    __shared__ float hv[4][HID];
    __shared__ float tv[4][HID];
    int tid = threadIdx.x;
    for (int idx = tid; idx < HID * HID / 4; idx += 256)
        ((float4*)rw)[idx] = ((const float4*)root_w)[idx];
    for (int idx = tid; idx < HID * LAT / 4; idx += 256)
        ((float4*)mw)[idx] = ((const float4*)mu_w)[idx];
    for (int idx = tid; idx < HID * LAT / 4; idx += 256)
        ((float4*)lw)[idx] = ((const float4*)lv_w)[idx];
    __syncthreads();

    int g = tid >> 6;
    int o = tid & 63;
    float cb = conv_b[o];
    float hb = (o < LAT) ? mu_b[o] : lv_b[o - LAT];

    for (int nl = g; nl < 16; nl += 4) {
        int n = blockIdx.x * 16 + nl;
        bool valid = n < N;
        if (valid) hv[g][o] = g_h[(size_t)n * HID + o];
        asm volatile("bar.sync %0, 64;" :: "r"(g + 1) : "memory");
        if (valid) {
            float inv = 1.f / fmaxf(g_cnt[n], 1.f);
            float acc = cb + g_num[(size_t)n * HID + o] * inv;
#pragma unroll
            for (int h = 0; h < HID; h++) acc += hv[g][h] * rw[h][o];
            tv[g][o] = fmaxf(acc, 0.f);
        }
        asm volatile("bar.sync %0, 64;" :: "r"(g + 1) : "memory");
        if (valid) {
            if (o < LAT) {
                float m = hb;
#pragma unroll
                for (int k = 0; k < HID; k++) m += tv[g][k] * mw[k][o];
                out[(size_t)n * LAT + o] = m;
            } else {
                int l = o - LAT;
                float m = hb;
#pragma unroll
                for (int k = 0; k < HID; k++) m += tv[g][k] * lw[k][l];
                out[(size_t)N * LAT + (size_t)n * LAT + l] = m;
            }
        }
        asm volatile("bar.sync %0, 64;" :: "r"(g + 1) : "memory");
    }
}

// ---------------- launcher ---------------------------------------------------
extern "C" void kernel_launch(void* const* d_in, const int* in_sizes, int n_in,
                              void* d_out, int out_size) {
    const float* x      = (const float*)d_in[0];
    const void*  ei     = d_in[1];
    const float* ea     = (const float*)d_in[2];
    const float* lin_w  = (const float*)d_in[3];
    const float* lin_b  = (const float*)d_in[4];
    const float* ker_w  = (const float*)d_in[5];
    const float* ker_b  = (const float*)d_in[6];
    const float* root_w = (const float*)d_in[7];
    const float* conv_b = (const float*)d_in[8];
    const float* mu_w   = (const float*)d_in[9];
    const float* mu_b   = (const float*)d_in[10];
    const float* lv_w   = (const float*)d_in[11];
    const float* lv_b   = (const float*)d_in[12];

    int N = in_sizes[0] / IN_DIM;
    int E = in_sizes[1] / 2;
    if (N > NMAX) N = NMAX;
    if (E > EMAX) E = EMAX;

    cudaFuncSetAttribute(edge_kernel, cudaFuncAttributeMaxDynamicSharedMemorySize,
                         SMEM_EDGE);

    int ntiles = (E + 127) / 128;
    int grid   = (ntiles < EDGE_GRID) ? ntiles : EDGE_GRID;

    setup_kernel<<<640, 256>>>((const int*)ei, ker_w, ker_b, N);
    convert_kernel<<<(E + 255) / 256, 256>>>(ei, E);
    hin_kernel<<<(N + 15) / 16, 128>>>(x, lin_w, lin_b, N);
    edge_kernel<<<grid, 256, SMEM_EDGE>>>(ea, E, ntiles);
    final_kernel<<<(N + 15) / 16, 256>>>(root_w, conv_b, mu_w, mu_b, lv_w, lv_b,
                                         (float*)d_out, N);
}

// round 13
// speedup vs baseline: 1.2852x; 1.0206x over previous
#include <cuda_runtime.h>
#include <cuda_bf16.h>
#include <cstdint>

// Problem constants (shapes fixed by the reference: N=20000, E=100000)
#define NMAX 20000
#define EMAX 100000
constexpr int IN_DIM = 128;
constexpr int HID    = 64;
constexpr int LAT    = 32;
constexpr int EDIM   = 16;

// ---------------- edge kernel geometry --------------------------------------
constexpr int B_CHUNK_BYTES = 256 * 48;          // bh image: 12288
constexpr int B_BIAS_OFF    = B_CHUNK_BYTES;     // 12288
constexpr int B_SLOT_BYTES  = B_BIAS_OFF + 1024; // bh + bias: 13312
constexpr int NCHUNK        = 16;
constexpr int EDGE_GRID     = 444;

constexpr int SMB_A    = 0;                       // 2 terms * 128*48 = 12288
constexpr int SMB_B    = 12288;                   // 2 slots * 13312 = 26624
constexpr int SMEM_EDGE = SMB_B + 2 * B_SLOT_BYTES;   // 38912 (3 CTAs/SM)

// ---------------- pre kernel block partition ---------------------------------
constexpr int PRE_SETUP_BLOCKS = 320;             // zero + B prep + ticket
constexpr int PRE_CONV_BLOCKS  = 782;             // edge-index convert (128/blk)
constexpr int PRE_HIN_BLOCKS   = 1250;            // hin GEMM (16 nodes/blk)
constexpr int PRE_GRID = PRE_SETUP_BLOCKS + PRE_CONV_BLOCKS + PRE_HIN_BLOCKS;

// ---------------- scratch (device globals; no cudaMalloc allowed) -----------
__device__ float g_h[NMAX * HID];
__device__ float g_num[NMAX * HID];
__device__ float g_cnt[NMAX];
__device__ int   g_src[EMAX];
__device__ int   g_dst[EMAX];
__device__ int   g_ticket;
__device__ __align__(16) unsigned char g_Bp[NCHUNK * B_SLOT_BYTES]; // 208KB

// ---------------- helpers ----------------------------------------------------
typedef unsigned long long u64;

__device__ __forceinline__ u64 pk2(float x, float y) {
    u64 r; asm("mov.b64 %0,{%1,%2};" : "=l"(r) : "f"(x), "f"(y)); return r;
}
__device__ __forceinline__ void upk2(u64 v, float& x, float& y) {
    asm("mov.b64 {%0,%1},%2;" : "=f"(x), "=f"(y) : "l"(v));
}
__device__ __forceinline__ u64 ffma2(u64 a, u64 b, u64 c) {
    u64 d; asm("fma.rn.f32x2 %0,%1,%2,%3;" : "=l"(d) : "l"(a), "l"(b), "l"(c)); return d;
}
__device__ __forceinline__ unsigned smem_u32(const void* p) {
    return (unsigned)__cvta_generic_to_shared(p);
}
__device__ __forceinline__ void cpasync16(unsigned dst, const void* src) {
    asm volatile("cp.async.ca.shared.global [%0], [%1], 16;" :: "r"(dst), "l"(src));
}
#define CP_COMMIT() asm volatile("cp.async.commit_group;" ::: "memory")
#define CP_WAIT0()  asm volatile("cp.async.wait_group 0;" ::: "memory")

#define LDMX4(r, addr) \
    asm volatile("ldmatrix.sync.aligned.m8n8.x4.shared.b16 {%0,%1,%2,%3},[%4];" \
                 : "=r"((r)[0]), "=r"((r)[1]), "=r"((r)[2]), "=r"((r)[3]) : "r"(addr))

#define MMA_BF16(c0, c1, c2, c3, a, b0, b1) \
    asm volatile("mma.sync.aligned.m16n8k16.row.col.f32.bf16.bf16.f32 " \
                 "{%0,%1,%2,%3},{%4,%5,%6,%7},{%8,%9},{%0,%1,%2,%3};" \
                 : "+f"(c0), "+f"(c1), "+f"(c2), "+f"(c3) \
                 : "r"((a)[0]), "r"((a)[1]), "r"((a)[2]), "r"((a)[3]), \
                   "r"(b0), "r"(b1))

// ---------------- pre: setup | convert | hin (block-partitioned, concurrent) -
__global__ void __launch_bounds__(128) pre_kernel(
    const int* __restrict__ ei,
    const float* __restrict__ kw, const float* __restrict__ kb,
    const float* __restrict__ x, const float* __restrict__ lw,
    const float* __restrict__ lb, int N, int E) {
    int bid = blockIdx.x, tid = threadIdx.x;

    if (bid < PRE_SETUP_BLOCKS) {
        // -------- setup: zero accumulators, prep B image, reset ticket ------
        int stid = bid * 128 + tid;
        int ssz  = PRE_SETUP_BLOCKS * 128;
        if (stid == 0) g_ticket = 0;
        int tot = N * HID;
        for (int i = stid; i < tot; i += ssz) g_num[i] = 0.f;
        for (int j = stid; j < N; j += ssz)   g_cnt[j] = 0.f;
        for (int idx = stid; idx < 4096 * 16; idx += ssz) {
            int n = idx >> 4, k = idx & 15;
            float v = kw[(size_t)k * 4096 + n];
            int c = n >> 8, nl = n & 255;
            *(__nv_bfloat16*)(g_Bp + (size_t)c * B_SLOT_BYTES + (size_t)nl * 48
                              + (size_t)k * 2) = __float2bfloat16_rn(v);
        }
        // bias arranged for one LDS.v4 per jp
        for (int n = stid; n < 4096; n += ssz) {
            int c = n >> 8, nl = n & 255;
            int jj = nl >> 3, col8 = nl & 7;
            int q = col8 >> 1, lo = col8 & 1;
            int pairidx = jj >> 1, odd = jj & 1;
            size_t off = (size_t)pairidx * 64 + (size_t)q * 16 + (size_t)odd * 8
                       + (size_t)lo * 4;
            *(float*)(g_Bp + (size_t)c * B_SLOT_BYTES + B_BIAS_OFF + off) = kb[n];
        }
        return;
    }

    if (bid < PRE_SETUP_BLOCKS + PRE_CONV_BLOCKS) {
        // -------- convert: edge_index -> g_src/g_dst (dtype auto-detect) ----
        int e = (bid - PRE_SETUP_BLOCKS) * 128 + tid;
        if (e >= E) return;
        // per-thread is64 detection: int64 LE buffer has odd words == 0 for
        // values in [0, N); 32 samples of broadcast L2 reads.
        int is64 = 1;
#pragma unroll
        for (int k = 0; k < 32; k++)
            if (__ldg(ei + 2 * k + 1) != 0) is64 = 0;
        int s, d;
        if (is64) {
            const long long* p = (const long long*)ei;
            s = (int)p[e]; d = (int)p[E + e];
        } else {
            s = ei[e]; d = ei[E + e];
        }
        g_src[e] = s; g_dst[e] = d;
        // (degree counting moved to edge_kernel scatter: zero->count ordering)
        return;
    }

    // -------- hin: g_h = relu(x @ lin_in_w + lin_in_b), 16 nodes/block ------
    {
        __shared__ u64   ws2[IN_DIM][32];   // (w[d][2p], w[d][2p+1])
        __shared__ float xs[16][IN_DIM];
        int hblk = bid - PRE_SETUP_BLOCKS - PRE_CONV_BLOCKS;
        for (int i = tid; i < IN_DIM * 32; i += 128)
            ((u64*)ws2)[i] = ((const u64*)lw)[i];
        int base = hblk * 16;
        for (int i = tid; i < 16 * 32; i += 128) {
            int nl = i >> 5, j = i & 31;
            int n = base + nl;
            if (n < N) ((float4*)xs[nl])[j] = ((const float4*)(x + (size_t)n * IN_DIM))[j];
        }
        __syncthreads();
        int p = tid & 31, g = tid >> 5;
        float2 b2 = ((const float2*)lb)[p];
        u64 bias2 = pk2(b2.x, b2.y);
        u64 acc0 = bias2, acc1 = bias2, acc2 = bias2, acc3 = bias2;
#pragma unroll 8
        for (int d = 0; d < IN_DIM; d++) {
            u64 w2 = ws2[d][p];
            acc0 = ffma2(pk2(xs[g][d],      xs[g][d]),      w2, acc0);
            acc1 = ffma2(pk2(xs[g + 4][d],  xs[g + 4][d]),  w2, acc1);
            acc2 = ffma2(pk2(xs[g + 8][d],  xs[g + 8][d]),  w2, acc2);
            acc3 = ffma2(pk2(xs[g + 12][d], xs[g + 12][d]), w2, acc3);
        }
        u64 accs[4] = {acc0, acc1, acc2, acc3};
#pragma unroll
        for (int q = 0; q < 4; q++) {
            int n = base + g + 4 * q;
            if (n < N) {
                float v0, v1; upk2(accs[q], v0, v1);
                float2 r; r.x = fmaxf(v0, 0.f); r.y = fmaxf(v1, 0.f);
                *(float2*)(g_h + (size_t)n * HID + 2 * p) = r;
            }
        }
    }
}

// ---------------- fused edge kernel (mma.sync bf16 2-term, persistent) -------
__device__ __forceinline__ void stage_A(unsigned char* sm,
                                        const float* __restrict__ edge_attr,
                                        int tile, int E, int tid) {
    if (tid >= 128) return;
    int e = tile * 128 + tid;
    float va[16];
    if (e < E) {
        const float4* p = (const float4*)(edge_attr + (size_t)e * EDIM);
#pragma unroll
        for (int i = 0; i < 4; i++) {
            float4 q4 = p[i];
            va[4*i] = q4.x; va[4*i+1] = q4.y; va[4*i+2] = q4.z; va[4*i+3] = q4.w;
        }
    } else {
#pragma unroll
        for (int i = 0; i < 16; i++) va[i] = 0.f;
    }
#pragma unroll
    for (int k = 0; k < 8; k++) {
        float v0 = va[2*k], v1 = va[2*k+1];
        __nv_bfloat16 h0 = __float2bfloat16_rn(v0);
        __nv_bfloat16 h1 = __float2bfloat16_rn(v1);
        __nv_bfloat162 hp; hp.x = h0; hp.y = h1;
        __nv_bfloat162 lp;
        lp.x = __float2bfloat16_rn(v0 - __bfloat162float(h0));
        lp.y = __float2bfloat16_rn(v1 - __bfloat162float(h1));
        *(__nv_bfloat162*)(sm + SMB_A + tid * 48 + k * 4)        = hp;
        *(__nv_bfloat162*)(sm + SMB_A + 6144 + tid * 48 + k * 4) = lp;
    }
}

__global__ void __launch_bounds__(256, 3) edge_kernel(
    const float* __restrict__ edge_attr, int E, int ntiles) {
    extern __shared__ __align__(16) unsigned char sm[];
    __shared__ int s_tile;
    unsigned sb = smem_u32(sm);
    int tid = threadIdx.x, lane = tid & 31, w = tid >> 5;

    if (tid == 0) s_tile = atomicAdd(&g_ticket, 1);
    __syncthreads();
    int tile = s_tile;
    if (tile >= ntiles) return;

    stage_A(sm, edge_attr, tile, E, tid);

    // prefetch B chunk 0 -> slot 0
    for (int i = tid; i < B_SLOT_BYTES / 16; i += 256)
        cpasync16(sb + SMB_B + i * 16, g_Bp + i * 16);
    CP_COMMIT();
    CP_WAIT0();
    __syncthreads();

    int q = lane & 3;
    int row0 = lane >> 2;
    unsigned aaddr0 = sb + SMB_A +
        (unsigned)((w * 16 + (lane & 7) + ((lane >> 3) & 1) * 8) * 48 + (lane >> 4) * 16);
    unsigned bext = (unsigned)((lane & 7) * 48 + ((lane & 8) ? 16 : 0)
                               + ((lane & 16) ? 384 : 0));

    int cc = 0;
    while (true) {
        unsigned a_hi[4], a_lo[4];
        LDMX4(a_hi, aaddr0);
        LDMX4(a_lo, aaddr0 + 6144);

        int e0 = tile * 128 + w * 16 + row0;
        int e1 = e0 + 8;
        const float4* hp0 = (const float4*)(g_h + (size_t)((e0 < E) ? g_src[e0] : 0) * HID);
        const float4* hp1 = (const float4*)(g_h + (size_t)((e1 < E) ? g_src[e1] : 0) * HID);

        u64 msgA2[8], msgB2[8];      // packed f32x2 accumulators
#pragma unroll
        for (int i = 0; i < 8; i++) { msgA2[i] = 0ULL; msgB2[i] = 0ULL; }

#pragma unroll 1
        for (int c = 0; c < NCHUNK; c++, cc++) {
            int slot = cc & 1;
            {   // prefetch next chunk in the tile-independent sequence
                int nc = (cc + 1) & 15;
                const unsigned char* src = g_Bp + (size_t)nc * B_SLOT_BYTES;
                unsigned dstb = sb + SMB_B + (unsigned)(((cc + 1) & 1) * B_SLOT_BYTES);
                for (int i = tid; i < B_SLOT_BYTES / 16; i += 256)
                    cpasync16(dstb + i * 16, src + i * 16);
                CP_COMMIT();
            }
            unsigned slotbase = sb + SMB_B + (unsigned)(slot * B_SLOT_BYTES);
            unsigned bhib  = slotbase + bext;
            unsigned biasb = slotbase + (unsigned)B_BIAS_OFF + (unsigned)(q * 16);
            float4 hv0 = __ldg(hp0 + c);
            float4 hv1 = __ldg(hp1 + c);
            float h0a[4] = {hv0.x, hv0.y, hv0.z, hv0.w};
            float h1a[4] = {hv1.x, hv1.y, hv1.z, hv1.w};
#pragma unroll
            for (int hb = 0; hb < 4; hb++) {
                u64 h2a = pk2(h0a[hb], h0a[hb]);
                u64 h2b = pk2(h1a[hb], h1a[hb]);
#pragma unroll
                for (int jp = 0; jp < 4; jp++) {
                    int jj0 = hb * 8 + jp * 2;
                    unsigned bh[4];
                    LDMX4(bh, bhib + (unsigned)(jj0 * 384));
                    float bx, by, bz, bw;
                    asm("ld.shared.v4.f32 {%0,%1,%2,%3},[%4];"
                        : "=f"(bx), "=f"(by), "=f"(bz), "=f"(bw)
                        : "r"(biasb + (unsigned)((hb * 4 + jp) * 64)));
                    float c0 = bx, c1 = by, c2 = bx, c3 = by;
                    float d0 = bz, d1 = bw, d2 = bz, d3 = bw;
                    MMA_BF16(c0, c1, c2, c3, a_hi, bh[0], bh[1]);
                    MMA_BF16(d0, d1, d2, d3, a_hi, bh[2], bh[3]);
                    MMA_BF16(c0, c1, c2, c3, a_lo, bh[0], bh[1]);
                    MMA_BF16(d0, d1, d2, d3, a_lo, bh[2], bh[3]);
                    float r0 = fmaxf(c0, 0.f), r1 = fmaxf(c1, 0.f);
                    float r2 = fmaxf(c2, 0.f), r3 = fmaxf(c3, 0.f);
                    float s0 = fmaxf(d0, 0.f), s1 = fmaxf(d1, 0.f);
                    float s2 = fmaxf(d2, 0.f), s3 = fmaxf(d3, 0.f);
                    msgA2[2*jp]     = ffma2(h2a, pk2(r0, r1), msgA2[2*jp]);
                    msgB2[2*jp]     = ffma2(h2b, pk2(r2, r3), msgB2[2*jp]);
                    msgA2[2*jp + 1] = ffma2(h2a, pk2(s0, s1), msgA2[2*jp + 1]);
                    msgB2[2*jp + 1] = ffma2(h2b, pk2(s2, s3), msgB2[2*jp + 1]);
                }
            }
            CP_WAIT0();
            __syncthreads();
        }

        // scatter: each (edge, o) has a unique owner thread; msgX2[i] <-> o = 8i + 2q
        if (e0 < E) {
            int dst = g_dst[e0];
            float* d = g_num + (size_t)dst * HID + 2 * q;
#pragma unroll
            for (int i = 0; i < 8; i++) {
                float v0, v1; upk2(msgA2[i], v0, v1);
                atomicAdd(d + 8 * i,     v0);
                atomicAdd(d + 8 * i + 1, v1);
            }
            if (q == 0) atomicAdd(&g_cnt[dst], 1.f);   // degree count
        }
        if (e1 < E) {
            int dst = g_dst[e1];
            float* d = g_num + (size_t)dst * HID + 2 * q;
#pragma unroll
            for (int i = 0; i < 8; i++) {
                float v0, v1; upk2(msgB2[i], v0, v1);
                atomicAdd(d + 8 * i,     v0);
                atomicAdd(d + 8 * i + 1, v1);
            }
            if (q == 0) atomicAdd(&g_cnt[dst], 1.f);   // degree count
        }

        // next tile from the ticket
        if (tid == 0) s_tile = atomicAdd(&g_ticket, 1);
        __syncthreads();
        tile = s_tile;
        if (tile >= ntiles) break;
        stage_A(sm, edge_attr, tile, E, tid);
        __syncthreads();
    }
}

// ---------------- final: relu(h@root_w + num/cnt + conv_b) -> mu/logvar -----
__global__ void __launch_bounds__(256) final_kernel(
    const float* __restrict__ root_w, const float* __restrict__ conv_b,
    const float* __restrict__ mu_w, const float* __restrict__ mu_b,
    const float* __restrict__ lv_w, const float* __restrict__ lv_b,
    float* __restrict__ out, int N) {
    __shared__ float rw[HID][HID];
    __shared__ float mw[HID][LAT];
    __shared__ float lw[HID][LAT];
    __shared__ float hv[4][HID];
    __shared__ float tv[4][HID];
    int tid = threadIdx.x;
    for (int idx = tid; idx < HID * HID / 4; idx += 256)
        ((float4*)rw)[idx] = ((const float4*)root_w)[idx];
    for (int idx = tid; idx < HID * LAT / 4; idx += 256)
        ((float4*)mw)[idx] = ((const float4*)mu_w)[idx];
    for (int idx = tid; idx < HID * LAT / 4; idx += 256)
        ((float4*)lw)[idx] = ((const float4*)lv_w)[idx];
    __syncthreads();

    int g = tid >> 6;
    int o = tid & 63;
    float cb = conv_b[o];
    float hb = (o < LAT) ? mu_b[o] : lv_b[o - LAT];

    for (int nl = g; nl < 16; nl += 4) {
        int n = blockIdx.x * 16 + nl;
        bool valid = n < N;
        if (valid) hv[g][o] = g_h[(size_t)n * HID + o];
        asm volatile("bar.sync %0, 64;" :: "r"(g + 1) : "memory");
        if (valid) {
            float inv = 1.f / fmaxf(g_cnt[n], 1.f);
            float acc = cb + g_num[(size_t)n * HID + o] * inv;
#pragma unroll
            for (int h = 0; h < HID; h++) acc += hv[g][h] * rw[h][o];
            tv[g][o] = fmaxf(acc, 0.f);
        }
        asm volatile("bar.sync %0, 64;" :: "r"(g + 1) : "memory");
        if (valid) {
            if (o < LAT) {
                float m = hb;
#pragma unroll
                for (int k = 0; k < HID; k++) m += tv[g][k] * mw[k][o];
                out[(size_t)n * LAT + o] = m;
            } else {
                int l = o - LAT;
                float m = hb;
#pragma unroll
                for (int k = 0; k < HID; k++) m += tv[g][k] * lw[k][l];
                out[(size_t)N * LAT + (size_t)n * LAT + l] = m;
            }
        }
        asm volatile("bar.sync %0, 64;" :: "r"(g + 1) : "memory");
    }
}

// ---------------- launcher ---------------------------------------------------
extern "C" void kernel_launch(void* const* d_in, const int* in_sizes, int n_in,
                              void* d_out, int out_size) {
    const float* x      = (const float*)d_in[0];
    const void*  ei     = d_in[1];
    const float* ea     = (const float*)d_in[2];
    const float* lin_w  = (const float*)d_in[3];
    const float* lin_b  = (const float*)d_in[4];
    const float* ker_w  = (const float*)d_in[5];
    const float* ker_b  = (const float*)d_in[6];
    const float* root_w = (const float*)d_in[7];
    const float* conv_b = (const float*)d_in[8];
    const float* mu_w   = (const float*)d_in[9];
    const float* mu_b   = (const float*)d_in[10];
    const float* lv_w   = (const float*)d_in[11];
    const float* lv_b   = (const float*)d_in[12];

    int N = in_sizes[0] / IN_DIM;
    int E = in_sizes[1] / 2;
    if (N > NMAX) N = NMAX;
    if (E > EMAX) E = EMAX;

    cudaFuncSetAttribute(edge_kernel, cudaFuncAttributeMaxDynamicSharedMemorySize,
                         SMEM_EDGE);

    int ntiles = (E + 127) / 128;
    int grid   = (ntiles < EDGE_GRID) ? ntiles : EDGE_GRID;

    pre_kernel<<<PRE_GRID, 128>>>((const int*)ei, ker_w, ker_b, x, lin_w, lin_b,
                                  N, E);
    edge_kernel<<<grid, 256, SMEM_EDGE>>>(ea, E, ntiles);
    final_kernel<<<(N + 15) / 16, 256>>>(root_w, conv_b, mu_w, mu_b, lv_w, lv_b,
                                         (float*)d_out, N);
}